// round 8
// baseline (speedup 1.0000x reference)
#include <cuda_runtime.h>
#include <cuda_fp16.h>
#include <math.h>
#include <stdint.h>

#define DQ 14
#define HID 32
#define DK 8
#define NS 240
#define DV 256
#define NTHREADS 1024
#define TILE_M 64
#define NKSTEP 15          // 240 / 16
#define AK 248             // A smem row stride in halves (496 B)
#define BKS 248            // B smem row stride in halves (496 B)
#define ABUF_BYTES (TILE_M * AK * 2)   // 31744

// ---- smem layout (bytes) ----
#define SO_W1P    0            // float[32][20] (pad, 14 used)
#define SO_B1     2560         // float[32]
#define SO_W2R    2688         // float[8][36]  (pad, 32 used)
#define SO_B2     3840         // float[8]
#define SO_KEYS   3872         // float[240][12] (pad, 8 used) = 11520
#define SO_H      15392        // float[16][32] = 2048
#define SO_RS     17440        // float[2][64] = 512
#define SO_A      17952        // 2 x half[64][AK] = 63488
#define SO_B      81440        // half[256][BKS] = 126976
#define SMEM_TOTAL 208416

#define BETA 2.0f

__device__ float g_attn_scratch[262144 * NS];

// ---------------------------------------------------------------------------
__device__ __forceinline__ uint32_t smem_u32(const void* p) {
    uint32_t a;
    asm("{ .reg .u64 t; cvta.to.shared.u64 t, %1; cvt.u32.u64 %0, t; }" : "=r"(a) : "l"(p));
    return a;
}
__device__ __forceinline__ void ldsm_x4(uint32_t& r0, uint32_t& r1, uint32_t& r2, uint32_t& r3,
                                        uint32_t addr) {
    asm volatile("ldmatrix.sync.aligned.m8n8.x4.shared.b16 {%0,%1,%2,%3}, [%4];"
                 : "=r"(r0), "=r"(r1), "=r"(r2), "=r"(r3) : "r"(addr));
}
__device__ __forceinline__ void mma16816(float* d, uint32_t a0, uint32_t a1, uint32_t a2,
                                         uint32_t a3, uint32_t b0, uint32_t b1) {
    asm volatile(
        "mma.sync.aligned.m16n8k16.row.col.f32.f16.f16.f32 "
        "{%0,%1,%2,%3}, {%4,%5,%6,%7}, {%8,%9}, {%0,%1,%2,%3};"
        : "+f"(d[0]), "+f"(d[1]), "+f"(d[2]), "+f"(d[3])
        : "r"(a0), "r"(a1), "r"(a2), "r"(a3), "r"(b0), "r"(b1));
}
__device__ __forceinline__ void sts_u16(uint32_t addr, unsigned short v) {
    asm volatile("st.shared.u16 [%0], %1;" :: "r"(addr), "h"(v) : "memory");
}
__device__ __forceinline__ uint32_t lds_u32(uint32_t addr) {
    uint32_t v;
    asm volatile("ld.shared.u32 %0, [%1];" : "=r"(v) : "r"(addr));
    return v;
}

// ---------------------------------------------------------------------------
// Producer: 4 rows of projection + softmax into A buffer (unnormalized e)
// ---------------------------------------------------------------------------
__device__ __forceinline__ void phaseA(
    const float* __restrict__ query, float* __restrict__ attn_out,
    char* smem, uint32_t abuf, float* rs,
    int pw, int lane, long row0)
{
    float* h_s = (float*)(smem + SO_H);
    float q8r[4][8];

    {   // ---- per-row projection: q8 for 4 rows ----
        const float4* w1v = (const float4*)(smem + SO_W1P + lane * 80);
        const float4 wa = w1v[0], wb = w1v[1], wc = w1v[2], wd2 = w1v[3];
        const float b1r = ((const float*)(smem + SO_B1))[lane];
        const int ci = lane & 7;
        const float b2r = ((const float*)(smem + SO_B2))[ci];
        const float4* w2v = (const float4*)(smem + SO_W2R + ci * 144);
        const float4* hv  = (const float4*)(h_s + pw * HID);

        #pragma unroll
        for (int rr = 0; rr < 4; rr++) {
            const long row = row0 + pw * 4 + rr;
            const float2* xp = (const float2*)(query + row * DQ);
            float xr[DQ];
            #pragma unroll
            for (int d = 0; d < 7; d++) {
                float2 v = __ldg(&xp[d]);
                xr[2 * d] = v.x; xr[2 * d + 1] = v.y;
            }
            float hj = b1r;
            hj = fmaf(wa.x, xr[0], hj);  hj = fmaf(wa.y, xr[1], hj);
            hj = fmaf(wa.z, xr[2], hj);  hj = fmaf(wa.w, xr[3], hj);
            hj = fmaf(wb.x, xr[4], hj);  hj = fmaf(wb.y, xr[5], hj);
            hj = fmaf(wb.z, xr[6], hj);  hj = fmaf(wb.w, xr[7], hj);
            hj = fmaf(wc.x, xr[8], hj);  hj = fmaf(wc.y, xr[9], hj);
            hj = fmaf(wc.z, xr[10], hj); hj = fmaf(wc.w, xr[11], hj);
            hj = fmaf(wd2.x, xr[12], hj); hj = fmaf(wd2.y, xr[13], hj);
            hj = 0.5f * hj * (1.0f + erff(hj * 0.7071067811865476f));
            h_s[pw * HID + lane] = hj;
            __syncwarp();

            float q = b2r;
            #pragma unroll
            for (int j4 = 0; j4 < 8; j4++) {
                const float4 h4 = hv[j4];
                const float4 w4 = w2v[j4];
                q = fmaf(w4.x, h4.x, q); q = fmaf(w4.y, h4.y, q);
                q = fmaf(w4.z, h4.z, q); q = fmaf(w4.w, h4.w, q);
            }
            __syncwarp();
            float ss = q * q;
            ss += __shfl_xor_sync(0xffffffffu, ss, 1);
            ss += __shfl_xor_sync(0xffffffffu, ss, 2);
            ss += __shfl_xor_sync(0xffffffffu, ss, 4);
            const float inv = 1.0f / fmaxf(sqrtf(ss), 1e-12f);
            const float qn = q * inv;
            #pragma unroll
            for (int i = 0; i < 8; i++)
                q8r[rr][i] = __shfl_sync(0xffffffffu, qn, i);
        }
    }

    // ---- t-loop: each key loaded once, used for 4 rows ----
    float ssum[4] = {0.f, 0.f, 0.f, 0.f};
    const uint32_t a_row_base = abuf + (pw * 4) * (AK * 2);
    #pragma unroll
    for (int t = 0; t < 8; t++) {
        const int k = lane + 32 * t;
        const float4* kv = (const float4*)(smem + SO_KEYS + k * 48);
        const float4 ka = kv[0];
        const float4 kb = kv[1];
        const bool valid = (k < NS);
        #pragma unroll
        for (int rr = 0; rr < 4; rr++) {
            float s = q8r[rr][0] * ka.x;
            s = fmaf(q8r[rr][1], ka.y, s);
            s = fmaf(q8r[rr][2], ka.z, s);
            s = fmaf(q8r[rr][3], ka.w, s);
            s = fmaf(q8r[rr][4], kb.x, s);
            s = fmaf(q8r[rr][5], kb.y, s);
            s = fmaf(q8r[rr][6], kb.z, s);
            s = fmaf(q8r[rr][7], kb.w, s);
            float e = __expf(BETA * (s - 1.0f));
            e = valid ? e : 0.f;
            ssum[rr] += e;
            if (valid)
                sts_u16(a_row_base + rr * (AK * 2) + k * 2,
                        __half_as_ushort(__float2half_rn(e)));
        }
    }
    #pragma unroll
    for (int rr = 0; rr < 4; rr++) {
        #pragma unroll
        for (int o = 16; o > 0; o >>= 1)
            ssum[rr] += __shfl_xor_sync(0xffffffffu, ssum[rr], o);
    }
    if (lane == 0) {
        rs[pw * 4 + 0] = ssum[0];
        rs[pw * 4 + 1] = ssum[1];
        rs[pw * 4 + 2] = ssum[2];
        rs[pw * 4 + 3] = ssum[3];
    }

    // ---- attn output: read back e, scale, store fp32 ----
    #pragma unroll
    for (int rr = 0; rr < 4; rr++) {
        const float invs = __fdividef(1.0f, ssum[rr]);
        float* arow = attn_out + (row0 + pw * 4 + rr) * NS;
        #pragma unroll
        for (int tp = 0; tp < 4; tp++) {
            const int idx = lane + 32 * tp;
            if (idx < NS / 2) {
                const uint32_t v = lds_u32(a_row_base + rr * (AK * 2) + idx * 4);
                const __half2 h2 = *(const __half2*)&v;
                const float2 f = __half22float2(h2);
                *(float2*)(arow + 2 * idx) = make_float2(f.x * invs, f.y * invs);
            }
        }
    }
}

// ---------------------------------------------------------------------------
// Consumer: content(64 x 256) = A(e) @ Bn^T with 32m x 32n warp tiles
// ---------------------------------------------------------------------------
__device__ __forceinline__ void phaseB(
    float* __restrict__ content,
    uint32_t abuf, uint32_t b_base, const float* rs,
    int cw, int lane, long row0)
{
    const int m0 = (cw & 1) * 32;
    const int n0 = (cw >> 1) * 32;

    float acc[2][4][4];
    #pragma unroll
    for (int i = 0; i < 2; i++)
        #pragma unroll
        for (int t = 0; t < 4; t++)
            #pragma unroll
            for (int j = 0; j < 4; j++) acc[i][t][j] = 0.f;

    const uint32_t a_lane0 = abuf
        + ((m0 + (lane & 15)) * AK + (lane >> 4) * 8) * 2;
    const uint32_t a_lane1 = a_lane0 + 16 * AK * 2;
    const uint32_t b_lane = b_base
        + ((n0 + ((lane >> 4) << 3) + (lane & 7)) * BKS
           + (((lane >> 3) & 1) * 8)) * 2;

    #pragma unroll
    for (int ks = 0; ks < NKSTEP; ks++) {
        uint32_t a0[4], a1[4];
        ldsm_x4(a0[0], a0[1], a0[2], a0[3], a_lane0 + ks * 32);
        ldsm_x4(a1[0], a1[1], a1[2], a1[3], a_lane1 + ks * 32);
        #pragma unroll
        for (int np = 0; np < 2; np++) {
            uint32_t b0, b1, b2, b3;
            ldsm_x4(b0, b1, b2, b3, b_lane + (np * 16 * BKS + ks * 16) * 2);
            mma16816(acc[0][2 * np],     a0[0], a0[1], a0[2], a0[3], b0, b1);
            mma16816(acc[0][2 * np + 1], a0[0], a0[1], a0[2], a0[3], b2, b3);
            mma16816(acc[1][2 * np],     a1[0], a1[1], a1[2], a1[3], b0, b1);
            mma16816(acc[1][2 * np + 1], a1[0], a1[1], a1[2], a1[3], b2, b3);
        }
    }

    // epilogue: scale by 1/rowsum, store
    #pragma unroll
    for (int i = 0; i < 2; i++) {
        const int lrA = m0 + i * 16 + (lane >> 2);
        const float invA = __fdividef(1.0f, rs[lrA]);
        const float invB = __fdividef(1.0f, rs[lrA + 8]);
        const long r0 = row0 + lrA;
        const int cofs = (lane & 3) * 2;
        #pragma unroll
        for (int t = 0; t < 4; t++) {
            const int col = n0 + t * 8 + cofs;
            *(float2*)(content + r0 * DV + col) =
                make_float2(acc[i][t][0] * invA, acc[i][t][1] * invA);
            *(float2*)(content + (r0 + 8) * DV + col) =
                make_float2(acc[i][t][2] * invB, acc[i][t][3] * invB);
        }
    }
}

// ---------------------------------------------------------------------------
__global__ __launch_bounds__(NTHREADS, 1) void fused_kernel(
    const float* __restrict__ query,
    const float* __restrict__ W1, const float* __restrict__ b1,
    const float* __restrict__ W2, const float* __restrict__ b2,
    const float* __restrict__ values,
    const float* __restrict__ keys,
    float* __restrict__ content,
    float* __restrict__ attn_out,
    int nrows, int ntiles)
{
    extern __shared__ char smem[];
    const uint32_t smem_base = smem_u32(smem);
    const uint32_t a_base = smem_base + SO_A;
    const uint32_t b_base = smem_base + SO_B;
    float* rs_s = (float*)(smem + SO_RS);

    const int tid  = threadIdx.x;
    const int warp = tid >> 5;
    const int lane = tid & 31;

    // ---- one-time setup: weights/keys (padded for vector loads) ----
    {
        float* W1p = (float*)(smem + SO_W1P);
        for (int i = tid; i < HID * 20; i += NTHREADS) {
            int r = i / 20, d = i % 20;
            W1p[i] = (d < DQ) ? W1[r * DQ + d] : 0.f;
        }
        float* B1s = (float*)(smem + SO_B1);
        for (int i = tid; i < HID; i += NTHREADS) B1s[i] = b1[i];
        float* W2r = (float*)(smem + SO_W2R);
        for (int i = tid; i < DK * 36; i += NTHREADS) {
            int r = i / 36, j = i % 36;
            W2r[i] = (j < HID) ? W2[r * HID + j] : 0.f;
        }
        float* B2s = (float*)(smem + SO_B2);
        for (int i = tid; i < DK; i += NTHREADS) B2s[i] = b2[i];
        float* K12 = (float*)(smem + SO_KEYS);
        for (int i = tid; i < NS * 12; i += NTHREADS) {
            int k = i / 12, c = i % 12;
            K12[i] = (c < DK) ? keys[k * DK + c] : 0.f;
        }
        // Bn[n][k] fp16 (n-major transpose of values[k][n])
        for (int i = tid; i < NS * (DV / 2); i += NTHREADS) {
            const int k  = i / (DV / 2);
            const int np = i % (DV / 2);
            const float2 v = __ldg((const float2*)(values + k * DV + 2 * np));
            sts_u16(b_base + ((2 * np)     * BKS + k) * 2,
                    __half_as_ushort(__float2half_rn(v.x)));
            sts_u16(b_base + ((2 * np + 1) * BKS + k) * 2,
                    __half_as_ushort(__float2half_rn(v.y)));
        }
    }
    __syncthreads();

    const bool is_prod = (warp < 16);

    // ---- prologue: producers fill buf 0 with this CTA's first tile ----
    if (is_prod && blockIdx.x < ntiles) {
        phaseA(query, attn_out, smem, a_base, rs_s, warp, lane,
               (long)blockIdx.x * TILE_M);
    }
    __syncthreads();

    int i = 0;
    for (long t = blockIdx.x; t < ntiles; t += gridDim.x, i++) {
        const int cur = i & 1;
        const int nxt = cur ^ 1;
        if (is_prod) {
            const long nt = t + gridDim.x;
            if (nt < ntiles)
                phaseA(query, attn_out, smem, a_base + nxt * ABUF_BYTES,
                       rs_s + nxt * 64, warp, lane, nt * TILE_M);
        } else {
            phaseB(content, a_base + cur * ABUF_BYTES, b_base,
                   rs_s + cur * 64, warp - 16, lane, t * TILE_M);
        }
        __syncthreads();
    }
}

// ---------------------------------------------------------------------------
extern "C" void kernel_launch(void* const* d_in, const int* in_sizes, int n_in,
                              void* d_out, int out_size)
{
    const float* query  = (const float*)d_in[0];
    const float* W1     = (const float*)d_in[1];
    const float* b1     = (const float*)d_in[2];
    const float* W2     = (const float*)d_in[3];
    const float* b2     = (const float*)d_in[4];
    const float* values = (const float*)d_in[5];
    const float* keys   = (const float*)d_in[6];

    const int nrows  = in_sizes[0] / DQ;   // 262144
    const int ntiles = (nrows + TILE_M - 1) / TILE_M;

    float* out = (float*)d_out;
    float* content = out;
    float* attn;
    float* scratch;
    cudaGetSymbolAddress((void**)&scratch, g_attn_scratch);
    if ((long)out_size >= (long)nrows * (DV + NS)) {
        attn = out + (long)nrows * DV;
    } else {
        attn = scratch;
    }

    cudaFuncSetAttribute(fused_kernel, cudaFuncAttributeMaxDynamicSharedMemorySize,
                         SMEM_TOTAL);

    fused_kernel<<<152, NTHREADS, SMEM_TOTAL>>>(
        query, W1, b1, W2, b2, values, keys, content, attn, nrows, ntiles);
}

// round 10
// speedup vs baseline: 1.0644x; 1.0644x over previous
#include <cuda_runtime.h>
#include <cuda_fp16.h>
#include <math.h>
#include <stdint.h>

#define DQ 14
#define HID 32
#define DK 8
#define NS 240
#define DV 256
#define NTHREADS 1024
#define TILE_M 128
#define NKSTEP 15          // 240 / 16
#define AK 248             // A smem row stride in halves (496 B)
#define BKS 248            // B smem row stride in halves (496 B)

// ---- smem layout (bytes) ----
#define SO_W1P    0            // float[32][20] (pad, 14 used)
#define SO_B1     2560         // float[32]
#define SO_W2R    2688         // float[8][36]  (pad, 32 used)
#define SO_B2     3840         // float[8]
#define SO_KEYS   3872         // float[256][12] (pad rows+cols) = 12288
#define SO_H      16160        // float[32][32] = 4096
#define SO_RS     20256        // float[128]
#define SO_A      20768        // half[128][AK] = 63488 (unnormalized e)
#define SO_B      84256        // half[256][BKS] = 126976 (values, n-major)
#define SMEM_TOTAL 211232

#define BETA 2.0f
// BETA * log2(e)
#define CLOG2E 2.88539008177792681f

__device__ float g_attn_scratch[262144 * NS];

// ---------------------------------------------------------------------------
__device__ __forceinline__ uint32_t smem_u32(const void* p) {
    uint32_t a;
    asm("{ .reg .u64 t; cvta.to.shared.u64 t, %1; cvt.u32.u64 %0, t; }" : "=r"(a) : "l"(p));
    return a;
}
__device__ __forceinline__ void ldsm_x4(uint32_t& r0, uint32_t& r1, uint32_t& r2, uint32_t& r3,
                                        uint32_t addr) {
    asm volatile("ldmatrix.sync.aligned.m8n8.x4.shared.b16 {%0,%1,%2,%3}, [%4];"
                 : "=r"(r0), "=r"(r1), "=r"(r2), "=r"(r3) : "r"(addr));
}
__device__ __forceinline__ void mma16816(float* d, uint32_t a0, uint32_t a1, uint32_t a2,
                                         uint32_t a3, uint32_t b0, uint32_t b1) {
    asm volatile(
        "mma.sync.aligned.m16n8k16.row.col.f32.f16.f16.f32 "
        "{%0,%1,%2,%3}, {%4,%5,%6,%7}, {%8,%9}, {%0,%1,%2,%3};"
        : "+f"(d[0]), "+f"(d[1]), "+f"(d[2]), "+f"(d[3])
        : "r"(a0), "r"(a1), "r"(a2), "r"(a3), "r"(b0), "r"(b1));
}
__device__ __forceinline__ void sts_u16(uint32_t addr, unsigned short v) {
    asm volatile("st.shared.u16 [%0], %1;" :: "r"(addr), "h"(v) : "memory");
}
__device__ __forceinline__ uint32_t lds_u32(uint32_t addr) {
    uint32_t v;
    asm volatile("ld.shared.u32 %0, [%1];" : "=r"(v) : "r"(addr));
    return v;
}

// Fast 2^y for y in ~[-6, 0]: magic-constant round + deg-5 Taylor + exp patch.
// All fixed-latency fma/alu ops — no MUFU.
__device__ __forceinline__ float exp2_fast(float y) {
    const float magic = 12582912.0f;          // 2^23 + 2^22 (round-to-nearest)
    const float t = y + magic;
    const int   j = __float_as_int(t);        // low bits = round(y) as int
    const float f = y - (t - magic);          // f in [-0.5, 0.5]
    float p = 0.00133335581f;
    p = fmaf(p, f, 0.00961812911f);
    p = fmaf(p, f, 0.05550410866f);
    p = fmaf(p, f, 0.24022650696f);
    p = fmaf(p, f, 0.69314718056f);
    p = fmaf(p, f, 1.0f);
    return __int_as_float(__float_as_int(p) + (j << 23));
}

// ---------------------------------------------------------------------------
__global__ __launch_bounds__(NTHREADS, 1) void fused_kernel(
    const float* __restrict__ query,
    const float* __restrict__ W1, const float* __restrict__ b1,
    const float* __restrict__ W2, const float* __restrict__ b2,
    const float* __restrict__ values,
    const float* __restrict__ keys,
    float* __restrict__ content,
    float* __restrict__ attn_out,
    int nrows, int ntiles)
{
    extern __shared__ char smem[];
    float* b1_s   = (float*)(smem + SO_B1);
    float* b2_s   = (float*)(smem + SO_B2);
    float* h_s    = (float*)(smem + SO_H);
    float* rs_s   = (float*)(smem + SO_RS);

    const uint32_t smem_base = smem_u32(smem);
    const uint32_t a_base = smem_base + SO_A;
    const uint32_t b_base = smem_base + SO_B;

    const int tid  = threadIdx.x;
    const int warp = tid >> 5;
    const int lane = tid & 31;

    // ---- one-time setup: weights/keys (padded for vector loads) ----
    {
        float* W1p = (float*)(smem + SO_W1P);
        for (int i = tid; i < HID * 20; i += NTHREADS) {
            int r = i / 20, d = i % 20;
            W1p[i] = (d < DQ) ? W1[r * DQ + d] : 0.f;
        }
        for (int i = tid; i < HID; i += NTHREADS) b1_s[i] = b1[i];
        float* W2r = (float*)(smem + SO_W2R);
        for (int i = tid; i < DK * 36; i += NTHREADS) {
            int r = i / 36, j = i % 36;
            W2r[i] = (j < HID) ? W2[r * HID + j] : 0.f;
        }
        for (int i = tid; i < DK; i += NTHREADS) b2_s[i] = b2[i];
        float* K12 = (float*)(smem + SO_KEYS);
        for (int i = tid; i < 256 * 12; i += NTHREADS) {
            int k = i / 12, c = i % 12;
            K12[i] = (k < NS && c < DK) ? keys[k * DK + c] : 0.f;
        }
        // Bn[n][k] fp16 (n-major transpose of values[k][n])
        for (int i = tid; i < NS * (DV / 2); i += NTHREADS) {
            const int k  = i / (DV / 2);
            const int np = i % (DV / 2);
            const float2 v = __ldg((const float2*)(values + k * DV + 2 * np));
            sts_u16(b_base + ((2 * np)     * BKS + k) * 2,
                    __half_as_ushort(__float2half_rn(v.x)));
            sts_u16(b_base + ((2 * np + 1) * BKS + k) * 2,
                    __half_as_ushort(__float2half_rn(v.y)));
        }
    }
    __syncthreads();

    for (int tile = blockIdx.x; tile < ntiles; tile += gridDim.x) {
        const long row0 = (long)tile * TILE_M;

        // ================= Phase A: projection + softmax ===================
        {
            float q8r[4][8];   // q8 * BETA*log2e, per row

            {   // ---- per-row projection: q8 for 4 rows ----
                const float4* w1v = (const float4*)(smem + SO_W1P + lane * 80);
                const float4 wa = w1v[0], wb = w1v[1], wc = w1v[2], wd2 = w1v[3];
                const float b1r = b1_s[lane];
                const int ci = lane & 7;
                const float b2r = b2_s[ci];
                const float4* w2v = (const float4*)(smem + SO_W2R + ci * 144);
                const float4* hv  = (const float4*)(h_s + warp * HID);

                #pragma unroll
                for (int rr = 0; rr < 4; rr++) {
                    const int  mloc = warp * 4 + rr;
                    const long row  = row0 + mloc;
                    const float2* xp = (const float2*)(query + row * DQ);
                    float xr[DQ];
                    #pragma unroll
                    for (int d = 0; d < 7; d++) {
                        float2 v = __ldg(&xp[d]);
                        xr[2 * d] = v.x; xr[2 * d + 1] = v.y;
                    }
                    float hj = b1r;
                    hj = fmaf(wa.x, xr[0], hj);  hj = fmaf(wa.y, xr[1], hj);
                    hj = fmaf(wa.z, xr[2], hj);  hj = fmaf(wa.w, xr[3], hj);
                    hj = fmaf(wb.x, xr[4], hj);  hj = fmaf(wb.y, xr[5], hj);
                    hj = fmaf(wb.z, xr[6], hj);  hj = fmaf(wb.w, xr[7], hj);
                    hj = fmaf(wc.x, xr[8], hj);  hj = fmaf(wc.y, xr[9], hj);
                    hj = fmaf(wc.z, xr[10], hj); hj = fmaf(wc.w, xr[11], hj);
                    hj = fmaf(wd2.x, xr[12], hj); hj = fmaf(wd2.y, xr[13], hj);
                    hj = 0.5f * hj * (1.0f + erff(hj * 0.7071067811865476f));
                    h_s[warp * HID + lane] = hj;
                    __syncwarp();

                    float q = b2r;
                    #pragma unroll
                    for (int j4 = 0; j4 < 8; j4++) {
                        const float4 h4 = hv[j4];
                        const float4 w4 = w2v[j4];
                        q = fmaf(w4.x, h4.x, q); q = fmaf(w4.y, h4.y, q);
                        q = fmaf(w4.z, h4.z, q); q = fmaf(w4.w, h4.w, q);
                    }
                    __syncwarp();
                    float ss = q * q;
                    ss += __shfl_xor_sync(0xffffffffu, ss, 1);
                    ss += __shfl_xor_sync(0xffffffffu, ss, 2);
                    ss += __shfl_xor_sync(0xffffffffu, ss, 4);
                    // fold 1/||q|| and BETA*log2e into the row's q8
                    const float inv = CLOG2E / fmaxf(sqrtf(ss), 1e-12f);
                    const float qn = q * inv;
                    #pragma unroll
                    for (int i = 0; i < 8; i++)
                        q8r[rr][i] = __shfl_sync(0xffffffffu, qn, i);
                }
            }

            // ---- t-loop: each key loaded once, used for 4 rows ----
            float ssum[4] = {0.f, 0.f, 0.f, 0.f};
            const uint32_t a_row_base = a_base + (warp * 4) * (AK * 2);
            #pragma unroll
            for (int t = 0; t < 8; t++) {
                const int k = lane + 32 * t;
                const float4* kv = (const float4*)(smem + SO_KEYS + k * 48);
                const float4 ka = kv[0];
                const float4 kb = kv[1];
                const bool valid = (k < NS);
                #pragma unroll
                for (int rr = 0; rr < 4; rr++) {
                    // y = BETA*log2e*(sim - 1); dot starts at -BETA*log2e
                    float y = fmaf(q8r[rr][0], ka.x, -CLOG2E);
                    y = fmaf(q8r[rr][1], ka.y, y);
                    y = fmaf(q8r[rr][2], ka.z, y);
                    y = fmaf(q8r[rr][3], ka.w, y);
                    y = fmaf(q8r[rr][4], kb.x, y);
                    y = fmaf(q8r[rr][5], kb.y, y);
                    y = fmaf(q8r[rr][6], kb.z, y);
                    y = fmaf(q8r[rr][7], kb.w, y);
                    float e = exp2_fast(y);
                    e = valid ? e : 0.f;
                    ssum[rr] += e;
                    if (valid)
                        sts_u16(a_row_base + rr * (AK * 2) + k * 2,
                                __half_as_ushort(__float2half_rn(e)));
                }
            }
            #pragma unroll
            for (int rr = 0; rr < 4; rr++) {
                #pragma unroll
                for (int o = 16; o > 0; o >>= 1)
                    ssum[rr] += __shfl_xor_sync(0xffffffffu, ssum[rr], o);
            }
            if (lane == 0) {
                rs_s[warp * 4 + 0] = ssum[0];
                rs_s[warp * 4 + 1] = ssum[1];
                rs_s[warp * 4 + 2] = ssum[2];
                rs_s[warp * 4 + 3] = ssum[3];
            }

            // ---- attn output: read back e, scale, store fp32 ----
            #pragma unroll
            for (int rr = 0; rr < 4; rr++) {
                const float invs = __fdividef(1.0f, ssum[rr]);
                float* arow = attn_out + (row0 + warp * 4 + rr) * NS;
                #pragma unroll
                for (int tp = 0; tp < 4; tp++) {
                    const int idx = lane + 32 * tp;
                    if (idx < NS / 2) {
                        const uint32_t v = lds_u32(a_row_base + rr * (AK * 2) + idx * 4);
                        const __half2 h2 = *(const __half2*)&v;
                        const float2 f = __half22float2(h2);
                        *(float2*)(arow + 2 * idx) = make_float2(f.x * invs, f.y * invs);
                    }
                }
            }
        }
        __syncthreads();

        // ===== Phase B: content = A(e) @ Bn^T, 32m x 32n warp tiles ========
        {
            const int m0 = (warp & 3) * 32;
            const int n0 = (warp >> 2) * 32;

            float acc[2][4][4];
            #pragma unroll
            for (int i = 0; i < 2; i++)
                #pragma unroll
                for (int t = 0; t < 4; t++)
                    #pragma unroll
                    for (int j = 0; j < 4; j++) acc[i][t][j] = 0.f;

            const uint32_t a_lane0 = a_base
                + ((m0 + (lane & 15)) * AK + (lane >> 4) * 8) * 2;
            const uint32_t a_lane1 = a_lane0 + 16 * AK * 2;
            const uint32_t b_lane = b_base
                + ((n0 + ((lane >> 4) << 3) + (lane & 7)) * BKS
                   + (((lane >> 3) & 1) * 8)) * 2;

            #pragma unroll
            for (int ks = 0; ks < NKSTEP; ks++) {
                uint32_t a0[4], a1[4];
                ldsm_x4(a0[0], a0[1], a0[2], a0[3], a_lane0 + ks * 32);
                ldsm_x4(a1[0], a1[1], a1[2], a1[3], a_lane1 + ks * 32);
                #pragma unroll
                for (int np = 0; np < 2; np++) {
                    uint32_t b0, b1, b2, b3;
                    ldsm_x4(b0, b1, b2, b3, b_lane + (np * 16 * BKS + ks * 16) * 2);
                    mma16816(acc[0][2 * np],     a0[0], a0[1], a0[2], a0[3], b0, b1);
                    mma16816(acc[0][2 * np + 1], a0[0], a0[1], a0[2], a0[3], b2, b3);
                    mma16816(acc[1][2 * np],     a1[0], a1[1], a1[2], a1[3], b0, b1);
                    mma16816(acc[1][2 * np + 1], a1[0], a1[1], a1[2], a1[3], b2, b3);
                }
            }

            // epilogue: scale by 1/rowsum, store
            #pragma unroll
            for (int i = 0; i < 2; i++) {
                const int lrA = m0 + i * 16 + (lane >> 2);
                const float invA = __fdividef(1.0f, rs_s[lrA]);
                const float invB = __fdividef(1.0f, rs_s[lrA + 8]);
                const long r0 = row0 + lrA;
                const int cofs = (lane & 3) * 2;
                #pragma unroll
                for (int t = 0; t < 4; t++) {
                    const int col = n0 + t * 8 + cofs;
                    *(float2*)(content + r0 * DV + col) =
                        make_float2(acc[i][t][0] * invA, acc[i][t][1] * invA);
                    *(float2*)(content + (r0 + 8) * DV + col) =
                        make_float2(acc[i][t][2] * invB, acc[i][t][3] * invB);
                }
            }
        }
        __syncthreads();   // A_s / rs_s fully consumed before next tile
    }
}

// ---------------------------------------------------------------------------
extern "C" void kernel_launch(void* const* d_in, const int* in_sizes, int n_in,
                              void* d_out, int out_size)
{
    const float* query  = (const float*)d_in[0];
    const float* W1     = (const float*)d_in[1];
    const float* b1     = (const float*)d_in[2];
    const float* W2     = (const float*)d_in[3];
    const float* b2     = (const float*)d_in[4];
    const float* values = (const float*)d_in[5];
    const float* keys   = (const float*)d_in[6];

    const int nrows  = in_sizes[0] / DQ;   // 262144
    const int ntiles = (nrows + TILE_M - 1) / TILE_M;

    float* out = (float*)d_out;
    float* content = out;
    float* attn;
    float* scratch;
    cudaGetSymbolAddress((void**)&scratch, g_attn_scratch);
    if ((long)out_size >= (long)nrows * (DV + NS)) {
        attn = out + (long)nrows * DV;
    } else {
        attn = scratch;
    }

    cudaFuncSetAttribute(fused_kernel, cudaFuncAttributeMaxDynamicSharedMemorySize,
                         SMEM_TOTAL);

    fused_kernel<<<152, NTHREADS, SMEM_TOTAL>>>(
        query, W1, b1, W2, b2, values, keys, content, attn, nrows, ntiles);
}

// round 11
// speedup vs baseline: 1.0910x; 1.0249x over previous
#include <cuda_runtime.h>
#include <cuda_fp16.h>
#include <math.h>
#include <stdint.h>

#define DQ 14
#define HID 32
#define DK 8
#define NS 240
#define DV 256
#define NTHREADS 1024
#define TILE_M 128
#define NKSTEP 15          // 240 / 16
#define AK 248             // A smem row stride in halves (496 B)
#define BKS 248            // B smem row stride in halves (496 B)

// ---- smem layout (bytes) ----
#define SO_W1P    0            // float[32][20] (pad, 14 used)
#define SO_B1     2560         // float[32]
#define SO_W2R    2688         // float[8][36]  (pad, 32 used)
#define SO_B2     3840         // float[8]
#define SO_KEYH   3872         // half[256][8] exact sqrt2-scaled keys = 4096
#define SO_H4     7968         // float[32][4][32] = 16384
#define SO_RS     24352        // float[128] = 512
#define SO_A      24864        // half[128][AK] = 63488 (unnormalized e)
#define SO_B      88352        // half[256][BKS] = 126976 (values, n-major)
#define SMEM_TOTAL 215328

#define BETA 2.0f
#define CLOG2E 2.88539008177792681f        // BETA * log2(e)
#define CSCALE 2.04027885f                 // BETA * log2(e) / sqrt(2)

__device__ float g_attn_scratch[262144 * NS];

// ---------------------------------------------------------------------------
__device__ __forceinline__ uint32_t smem_u32(const void* p) {
    uint32_t a;
    asm("{ .reg .u64 t; cvta.to.shared.u64 t, %1; cvt.u32.u64 %0, t; }" : "=r"(a) : "l"(p));
    return a;
}
__device__ __forceinline__ void ldsm_x4(uint32_t& r0, uint32_t& r1, uint32_t& r2, uint32_t& r3,
                                        uint32_t addr) {
    asm volatile("ldmatrix.sync.aligned.m8n8.x4.shared.b16 {%0,%1,%2,%3}, [%4];"
                 : "=r"(r0), "=r"(r1), "=r"(r2), "=r"(r3) : "r"(addr));
}
__device__ __forceinline__ void mma16816(float* d, uint32_t a0, uint32_t a1, uint32_t a2,
                                         uint32_t a3, uint32_t b0, uint32_t b1) {
    asm volatile(
        "mma.sync.aligned.m16n8k16.row.col.f32.f16.f16.f32 "
        "{%0,%1,%2,%3}, {%4,%5,%6,%7}, {%8,%9}, {%0,%1,%2,%3};"
        : "+f"(d[0]), "+f"(d[1]), "+f"(d[2]), "+f"(d[3])
        : "r"(a0), "r"(a1), "r"(a2), "r"(a3), "r"(b0), "r"(b1));
}
__device__ __forceinline__ void sts_u16(uint32_t addr, unsigned short v) {
    asm volatile("st.shared.u16 [%0], %1;" :: "r"(addr), "h"(v) : "memory");
}
__device__ __forceinline__ uint32_t lds_u32(uint32_t addr) {
    uint32_t v;
    asm volatile("ld.shared.u32 %0, [%1];" : "=r"(v) : "r"(addr));
    return v;
}
__device__ __forceinline__ void lds_v4(uint32_t addr, uint32_t& a, uint32_t& b,
                                       uint32_t& c, uint32_t& d) {
    asm volatile("ld.shared.v4.b32 {%0,%1,%2,%3}, [%4];"
                 : "=r"(a), "=r"(b), "=r"(c), "=r"(d) : "r"(addr));
}

// Fast 2^y: magic-constant round + deg-5 poly + exponent patch (no MUFU).
__device__ __forceinline__ float exp2_fast(float y) {
    const float magic = 12582912.0f;          // 2^23 + 2^22
    const float t = y + magic;
    const int   j = __float_as_int(t);
    const float f = y - (t - magic);          // f in [-0.5, 0.5]
    float p = 0.00133335581f;
    p = fmaf(p, f, 0.00961812911f);
    p = fmaf(p, f, 0.05550410866f);
    p = fmaf(p, f, 0.24022650696f);
    p = fmaf(p, f, 0.69314718056f);
    p = fmaf(p, f, 1.0f);
    return __int_as_float(__float_as_int(p) + (j << 23));
}

// ---------------------------------------------------------------------------
__global__ __launch_bounds__(NTHREADS, 1) void fused_kernel(
    const float* __restrict__ query,
    const float* __restrict__ W1, const float* __restrict__ b1,
    const float* __restrict__ W2, const float* __restrict__ b2,
    const float* __restrict__ values,
    const float* __restrict__ keys,
    float* __restrict__ content,
    float* __restrict__ attn_out,
    int nrows, int ntiles)
{
    extern __shared__ char smem[];
    float* b1_s   = (float*)(smem + SO_B1);
    float* b2_s   = (float*)(smem + SO_B2);
    float* h4_s   = (float*)(smem + SO_H4);
    float* rs_s   = (float*)(smem + SO_RS);

    const uint32_t smem_base = smem_u32(smem);
    const uint32_t a_base = smem_base + SO_A;
    const uint32_t b_base = smem_base + SO_B;
    const uint32_t k_base = smem_base + SO_KEYH;

    const int tid  = threadIdx.x;
    const int warp = tid >> 5;
    const int lane = tid & 31;

    // ---- one-time setup ----
    {
        float* W1p = (float*)(smem + SO_W1P);
        for (int i = tid; i < HID * 20; i += NTHREADS) {
            int r = i / 20, d = i % 20;
            W1p[i] = (d < DQ) ? W1[r * DQ + d] : 0.f;
        }
        for (int i = tid; i < HID; i += NTHREADS) b1_s[i] = b1[i];
        float* W2r = (float*)(smem + SO_W2R);
        for (int i = tid; i < DK * 36; i += NTHREADS) {
            int r = i / 36, j = i % 36;
            W2r[i] = (j < HID) ? W2[r * HID + j] : 0.f;
        }
        for (int i = tid; i < DK; i += NTHREADS) b2_s[i] = b2[i];
        // exact fp16 keys: keys_n * sqrt(2) = E8 roots, components {0,+-1,+-0.5}
        for (int i = tid; i < 256 * DK; i += NTHREADS) {
            int k = i / DK, c = i % DK;
            float v = (k < NS) ? keys[k * DK + c] * 1.41421356237f : 0.f;
            sts_u16(k_base + i * 2, __half_as_ushort(__float2half_rn(v)));
        }
        // Bn[n][k] fp16 (n-major transpose of values[k][n])
        for (int i = tid; i < NS * (DV / 2); i += NTHREADS) {
            const int k  = i / (DV / 2);
            const int np = i % (DV / 2);
            const float2 v = __ldg((const float2*)(values + k * DV + 2 * np));
            sts_u16(b_base + ((2 * np)     * BKS + k) * 2,
                    __half_as_ushort(__float2half_rn(v.x)));
            sts_u16(b_base + ((2 * np + 1) * BKS + k) * 2,
                    __half_as_ushort(__float2half_rn(v.y)));
        }
    }
    __syncthreads();

    for (int tile = blockIdx.x; tile < ntiles; tile += gridDim.x) {
        const long row0 = (long)tile * TILE_M;
        float ssum[4];

        // ================= Phase A: projection + softmax ===================
        {
            // ---- pass 1: hidden layer for 4 rows ----
            {
                const float4* w1v = (const float4*)(smem + SO_W1P + lane * 80);
                const float4 wa = w1v[0], wb = w1v[1], wc = w1v[2], wd2 = w1v[3];
                const float b1r = b1_s[lane];
                #pragma unroll
                for (int rr = 0; rr < 4; rr++) {
                    const long row = row0 + warp * 4 + rr;
                    const float2* xp = (const float2*)(query + row * DQ);
                    float xr[DQ];
                    #pragma unroll
                    for (int d = 0; d < 7; d++) {
                        float2 v = __ldg(&xp[d]);
                        xr[2 * d] = v.x; xr[2 * d + 1] = v.y;
                    }
                    float hj = b1r;
                    hj = fmaf(wa.x, xr[0], hj);  hj = fmaf(wa.y, xr[1], hj);
                    hj = fmaf(wa.z, xr[2], hj);  hj = fmaf(wa.w, xr[3], hj);
                    hj = fmaf(wb.x, xr[4], hj);  hj = fmaf(wb.y, xr[5], hj);
                    hj = fmaf(wb.z, xr[6], hj);  hj = fmaf(wb.w, xr[7], hj);
                    hj = fmaf(wc.x, xr[8], hj);  hj = fmaf(wc.y, xr[9], hj);
                    hj = fmaf(wc.z, xr[10], hj); hj = fmaf(wc.w, xr[11], hj);
                    hj = fmaf(wd2.x, xr[12], hj); hj = fmaf(wd2.y, xr[13], hj);
                    hj = 0.5f * hj * (1.0f + erff(hj * 0.7071067811865476f));
                    h4_s[warp * 128 + rr * 32 + lane] = hj;
                }
            }
            __syncwarp();

            // ---- pass 2: q8 for 4 rows, W2 fragments loaded once ----
            float q8r[4][8];
            {
                const int ci = lane & 7;
                const float b2r = b2_s[ci];
                float q[4] = {b2r, b2r, b2r, b2r};
                const float4* w2v = (const float4*)(smem + SO_W2R + ci * 144);
                const float4* hv  = (const float4*)(h4_s + warp * 128);
                #pragma unroll
                for (int j4 = 0; j4 < 8; j4++) {
                    const float4 w4 = w2v[j4];
                    #pragma unroll
                    for (int rr = 0; rr < 4; rr++) {
                        const float4 h4 = hv[rr * 8 + j4];
                        q[rr] = fmaf(w4.x, h4.x, q[rr]);
                        q[rr] = fmaf(w4.y, h4.y, q[rr]);
                        q[rr] = fmaf(w4.z, h4.z, q[rr]);
                        q[rr] = fmaf(w4.w, h4.w, q[rr]);
                    }
                }
                #pragma unroll
                for (int rr = 0; rr < 4; rr++) {
                    float ss = q[rr] * q[rr];
                    ss += __shfl_xor_sync(0xffffffffu, ss, 1);
                    ss += __shfl_xor_sync(0xffffffffu, ss, 2);
                    ss += __shfl_xor_sync(0xffffffffu, ss, 4);
                    // fold 1/||q|| and BETA*log2e/sqrt(2) into the row's q8
                    const float inv = CSCALE / fmaxf(sqrtf(ss), 1e-12f);
                    const float qn = q[rr] * inv;
                    #pragma unroll
                    for (int i = 0; i < 8; i++)
                        q8r[rr][i] = __shfl_sync(0xffffffffu, qn, i);
                }
            }

            // ---- t-loop: each key loaded once (LDS.128), used for 4 rows ----
            ssum[0] = ssum[1] = ssum[2] = ssum[3] = 0.f;
            const uint32_t a_row_base = a_base + (warp * 4) * (AK * 2);
            #pragma unroll
            for (int t = 0; t < 8; t++) {
                const int k = lane + 32 * t;
                uint32_t k0, k1, k2, k3;
                lds_v4(k_base + k * 16, k0, k1, k2, k3);
                const float2 ka0 = __half22float2(*(const __half2*)&k0);
                const float2 ka1 = __half22float2(*(const __half2*)&k1);
                const float2 kb0 = __half22float2(*(const __half2*)&k2);
                const float2 kb1 = __half22float2(*(const __half2*)&k3);
                const bool valid = (k < NS);
                #pragma unroll
                for (int rr = 0; rr < 4; rr++) {
                    // y = BETA*log2e*(sim - 1); dot vs sqrt2-scaled keys
                    float y = fmaf(q8r[rr][0], ka0.x, -CLOG2E);
                    y = fmaf(q8r[rr][1], ka0.y, y);
                    y = fmaf(q8r[rr][2], ka1.x, y);
                    y = fmaf(q8r[rr][3], ka1.y, y);
                    y = fmaf(q8r[rr][4], kb0.x, y);
                    y = fmaf(q8r[rr][5], kb0.y, y);
                    y = fmaf(q8r[rr][6], kb1.x, y);
                    y = fmaf(q8r[rr][7], kb1.y, y);
                    float e = exp2_fast(y);
                    e = valid ? e : 0.f;
                    ssum[rr] += e;
                    if (valid)
                        sts_u16(a_row_base + rr * (AK * 2) + k * 2,
                                __half_as_ushort(__float2half_rn(e)));
                }
            }
            #pragma unroll
            for (int rr = 0; rr < 4; rr++) {
                #pragma unroll
                for (int o = 16; o > 0; o >>= 1)
                    ssum[rr] += __shfl_xor_sync(0xffffffffu, ssum[rr], o);
            }
            if (lane == 0) {
                rs_s[warp * 4 + 0] = ssum[0];
                rs_s[warp * 4 + 1] = ssum[1];
                rs_s[warp * 4 + 2] = ssum[2];
                rs_s[warp * 4 + 3] = ssum[3];
            }
        }
        __syncthreads();

        // ===== Phase B region: attn store (overlaps) + MMA + epilogue ======
        {
            // ---- attn output (independent of MMA stream; fills issue gaps) ----
            const uint32_t a_row_base = a_base + (warp * 4) * (AK * 2);
            #pragma unroll
            for (int rr = 0; rr < 4; rr++) {
                const float invs = __fdividef(1.0f, ssum[rr]);
                float* arow = attn_out + (row0 + warp * 4 + rr) * NS;
                #pragma unroll
                for (int tp = 0; tp < 4; tp++) {
                    const int idx = lane + 32 * tp;
                    if (idx < NS / 2) {
                        const uint32_t v = lds_u32(a_row_base + rr * (AK * 2) + idx * 4);
                        const __half2 h2 = *(const __half2*)&v;
                        const float2 f = __half22float2(h2);
                        *(float2*)(arow + 2 * idx) = make_float2(f.x * invs, f.y * invs);
                    }
                }
            }

            // ---- GEMM: content = A(e) @ Bn^T, 32m x 32n warp tiles ----
            const int m0 = (warp & 3) * 32;
            const int n0 = (warp >> 2) * 32;

            float acc[2][4][4];
            #pragma unroll
            for (int i = 0; i < 2; i++)
                #pragma unroll
                for (int t = 0; t < 4; t++)
                    #pragma unroll
                    for (int j = 0; j < 4; j++) acc[i][t][j] = 0.f;

            const uint32_t a_lane0 = a_base
                + ((m0 + (lane & 15)) * AK + (lane >> 4) * 8) * 2;
            const uint32_t a_lane1 = a_lane0 + 16 * AK * 2;
            const uint32_t b_lane = b_base
                + ((n0 + ((lane >> 4) << 3) + (lane & 7)) * BKS
                   + (((lane >> 3) & 1) * 8)) * 2;

            #pragma unroll
            for (int ks = 0; ks < NKSTEP; ks++) {
                uint32_t a0[4], a1[4];
                ldsm_x4(a0[0], a0[1], a0[2], a0[3], a_lane0 + ks * 32);
                ldsm_x4(a1[0], a1[1], a1[2], a1[3], a_lane1 + ks * 32);
                #pragma unroll
                for (int np = 0; np < 2; np++) {
                    uint32_t b0, b1, b2, b3;
                    ldsm_x4(b0, b1, b2, b3, b_lane + (np * 16 * BKS + ks * 16) * 2);
                    mma16816(acc[0][2 * np],     a0[0], a0[1], a0[2], a0[3], b0, b1);
                    mma16816(acc[0][2 * np + 1], a0[0], a0[1], a0[2], a0[3], b2, b3);
                    mma16816(acc[1][2 * np],     a1[0], a1[1], a1[2], a1[3], b0, b1);
                    mma16816(acc[1][2 * np + 1], a1[0], a1[1], a1[2], a1[3], b2, b3);
                }
            }

            // epilogue: scale by 1/rowsum, store
            #pragma unroll
            for (int i = 0; i < 2; i++) {
                const int lrA = m0 + i * 16 + (lane >> 2);
                const float invA = __fdividef(1.0f, rs_s[lrA]);
                const float invB = __fdividef(1.0f, rs_s[lrA + 8]);
                const long r0 = row0 + lrA;
                const int cofs = (lane & 3) * 2;
                #pragma unroll
                for (int t = 0; t < 4; t++) {
                    const int col = n0 + t * 8 + cofs;
                    *(float2*)(content + r0 * DV + col) =
                        make_float2(acc[i][t][0] * invA, acc[i][t][1] * invA);
                    *(float2*)(content + (r0 + 8) * DV + col) =
                        make_float2(acc[i][t][2] * invB, acc[i][t][3] * invB);
                }
            }
        }
        __syncthreads();   // A_s / rs_s fully consumed before next tile
    }
}

// ---------------------------------------------------------------------------
extern "C" void kernel_launch(void* const* d_in, const int* in_sizes, int n_in,
                              void* d_out, int out_size)
{
    const float* query  = (const float*)d_in[0];
    const float* W1     = (const float*)d_in[1];
    const float* b1     = (const float*)d_in[2];
    const float* W2     = (const float*)d_in[3];
    const float* b2     = (const float*)d_in[4];
    const float* values = (const float*)d_in[5];
    const float* keys   = (const float*)d_in[6];

    const int nrows  = in_sizes[0] / DQ;   // 262144
    const int ntiles = (nrows + TILE_M - 1) / TILE_M;

    float* out = (float*)d_out;
    float* content = out;
    float* attn;
    float* scratch;
    cudaGetSymbolAddress((void**)&scratch, g_attn_scratch);
    if ((long)out_size >= (long)nrows * (DV + NS)) {
        attn = out + (long)nrows * DV;
    } else {
        attn = scratch;
    }

    cudaFuncSetAttribute(fused_kernel, cudaFuncAttributeMaxDynamicSharedMemorySize,
                         SMEM_TOTAL);

    fused_kernel<<<152, NTHREADS, SMEM_TOTAL>>>(
        query, W1, b1, W2, b2, values, keys, content, attn, nrows, ntiles);
}

// round 13
// speedup vs baseline: 1.1814x; 1.0829x over previous
#include <cuda_runtime.h>
#include <cuda_fp16.h>
#include <math.h>
#include <stdint.h>

#define DQ 14
#define HID 32
#define DK 8
#define NS 240
#define DV 256
#define NTHREADS 1024
#define TILE_M 128
#define NKSTEP 15          // 240 / 16
#define AK 248             // A smem row stride in halves (496 B)
#define BKS 248            // B smem row stride in halves (496 B)

// ---- smem layout (bytes) ----
#define SO_W1P    0            // float[32][20] (pad, 14 used)
#define SO_B1     2560         // float[32]
#define SO_W2R    2688         // float[8][36]  (pad, 32 used)
#define SO_B2     3840         // float[8]
#define SO_KEYH   3872         // half[256][8] exact sqrt2-scaled keys = 4096
#define SO_H4     7968         // float[32][4][32] = 16384
#define SO_Q8S    24352        // half[128][8] scaled q8 = 2048
#define SO_RSP    26400        // float[4][128] partial row sums = 2048
#define SO_A      28448        // half[128][AK] = 63488 (unnormalized e)
#define SO_B      91936        // half[256][BKS] = 126976 (values, n-major)
#define SMEM_TOTAL 218912

#define BETA 2.0f
#define CLOG2E 2.88539008177792681f        // BETA * log2(e)
#define CSCALE 2.04027885f                 // BETA * log2(e) / sqrt(2)

__device__ float g_attn_scratch[262144 * NS];

// ---------------------------------------------------------------------------
__device__ __forceinline__ uint32_t smem_u32(const void* p) {
    uint32_t a;
    asm("{ .reg .u64 t; cvta.to.shared.u64 t, %1; cvt.u32.u64 %0, t; }" : "=r"(a) : "l"(p));
    return a;
}
__device__ __forceinline__ void ldsm_x2(uint32_t& r0, uint32_t& r1, uint32_t addr) {
    asm volatile("ldmatrix.sync.aligned.m8n8.x2.shared.b16 {%0,%1}, [%2];"
                 : "=r"(r0), "=r"(r1) : "r"(addr));
}
__device__ __forceinline__ void ldsm_x4(uint32_t& r0, uint32_t& r1, uint32_t& r2, uint32_t& r3,
                                        uint32_t addr) {
    asm volatile("ldmatrix.sync.aligned.m8n8.x4.shared.b16 {%0,%1,%2,%3}, [%4];"
                 : "=r"(r0), "=r"(r1), "=r"(r2), "=r"(r3) : "r"(addr));
}
__device__ __forceinline__ void mma16816(float* d, uint32_t a0, uint32_t a1, uint32_t a2,
                                         uint32_t a3, uint32_t b0, uint32_t b1) {
    asm volatile(
        "mma.sync.aligned.m16n8k16.row.col.f32.f16.f16.f32 "
        "{%0,%1,%2,%3}, {%4,%5,%6,%7}, {%8,%9}, {%0,%1,%2,%3};"
        : "+f"(d[0]), "+f"(d[1]), "+f"(d[2]), "+f"(d[3])
        : "r"(a0), "r"(a1), "r"(a2), "r"(a3), "r"(b0), "r"(b1));
}
__device__ __forceinline__ void mma16808(float* d, uint32_t a0, uint32_t a1, uint32_t b0) {
    asm volatile(
        "mma.sync.aligned.m16n8k8.row.col.f32.f16.f16.f32 "
        "{%0,%1,%2,%3}, {%4,%5}, {%6}, {%0,%1,%2,%3};"
        : "+f"(d[0]), "+f"(d[1]), "+f"(d[2]), "+f"(d[3])
        : "r"(a0), "r"(a1), "r"(b0));
}
__device__ __forceinline__ void sts_u16(uint32_t addr, unsigned short v) {
    asm volatile("st.shared.u16 [%0], %1;" :: "r"(addr), "h"(v) : "memory");
}
__device__ __forceinline__ void sts_u32(uint32_t addr, uint32_t v) {
    asm volatile("st.shared.u32 [%0], %1;" :: "r"(addr), "r"(v) : "memory");
}
__device__ __forceinline__ uint32_t lds_u32(uint32_t addr) {
    uint32_t v;
    asm volatile("ld.shared.u32 %0, [%1];" : "=r"(v) : "r"(addr));
    return v;
}

// Fast 2^y: magic-constant round + deg-5 poly + exponent patch (no MUFU).
__device__ __forceinline__ float exp2_fast(float y) {
    const float magic = 12582912.0f;          // 2^23 + 2^22
    const float t = y + magic;
    const int   j = __float_as_int(t);
    const float f = y - (t - magic);          // f in [-0.5, 0.5]
    float p = 0.00133335581f;
    p = fmaf(p, f, 0.00961812911f);
    p = fmaf(p, f, 0.05550410866f);
    p = fmaf(p, f, 0.24022650696f);
    p = fmaf(p, f, 0.69314718056f);
    p = fmaf(p, f, 1.0f);
    return __int_as_float(__float_as_int(p) + (j << 23));
}

// ---------------------------------------------------------------------------
__global__ __launch_bounds__(NTHREADS, 1) void fused_kernel(
    const float* __restrict__ query,
    const float* __restrict__ W1, const float* __restrict__ b1,
    const float* __restrict__ W2, const float* __restrict__ b2,
    const float* __restrict__ values,
    const float* __restrict__ keys,
    float* __restrict__ content,
    float* __restrict__ attn_out,
    int nrows, int ntiles)
{
    extern __shared__ char smem[];
    float* b1_s   = (float*)(smem + SO_B1);
    float* b2_s   = (float*)(smem + SO_B2);
    float* h4_s   = (float*)(smem + SO_H4);
    float* rsp_s  = (float*)(smem + SO_RSP);

    const uint32_t smem_base = smem_u32(smem);
    const uint32_t a_base  = smem_base + SO_A;
    const uint32_t b_base  = smem_base + SO_B;
    const uint32_t k_base  = smem_base + SO_KEYH;
    const uint32_t q8_base = smem_base + SO_Q8S;

    const int tid  = threadIdx.x;
    const int warp = tid >> 5;
    const int lane = tid & 31;

    // ---- one-time setup ----
    {
        float* W1p = (float*)(smem + SO_W1P);
        for (int i = tid; i < HID * 20; i += NTHREADS) {
            int r = i / 20, d = i % 20;
            W1p[i] = (d < DQ) ? W1[r * DQ + d] : 0.f;
        }
        for (int i = tid; i < HID; i += NTHREADS) b1_s[i] = b1[i];
        float* W2r = (float*)(smem + SO_W2R);
        for (int i = tid; i < DK * 36; i += NTHREADS) {
            int r = i / 36, j = i % 36;
            W2r[i] = (j < HID) ? W2[r * HID + j] : 0.f;
        }
        for (int i = tid; i < DK; i += NTHREADS) b2_s[i] = b2[i];
        // exact fp16 keys: keys_n * sqrt(2) = E8 roots, components {0,+-1,+-0.5}
        for (int i = tid; i < 256 * DK; i += NTHREADS) {
            int k = i / DK, c = i % DK;
            float v = (k < NS) ? keys[k * DK + c] * 1.41421356237f : 0.f;
            sts_u16(k_base + i * 2, __half_as_ushort(__float2half_rn(v)));
        }
        // Bn[n][k] fp16 (n-major transpose of values[k][n])
        for (int i = tid; i < NS * (DV / 2); i += NTHREADS) {
            const int k  = i / (DV / 2);
            const int np = i % (DV / 2);
            const float2 v = __ldg((const float2*)(values + k * DV + 2 * np));
            sts_u16(b_base + ((2 * np)     * BKS + k) * 2,
                    __half_as_ushort(__float2half_rn(v.x)));
            sts_u16(b_base + ((2 * np + 1) * BKS + k) * 2,
                    __half_as_ushort(__float2half_rn(v.y)));
        }
    }
    __syncthreads();

    for (int tile = blockIdx.x; tile < ntiles; tile += gridDim.x) {
        const long row0 = (long)tile * TILE_M;

        // =========== R1: projection -> scaled q8 (fp16) in smem ============
        {
            // pass 1: hidden layer for 4 rows
            {
                const float4* w1v = (const float4*)(smem + SO_W1P + lane * 80);
                const float4 wa = w1v[0], wb = w1v[1], wc = w1v[2], wd2 = w1v[3];
                const float b1r = b1_s[lane];
                #pragma unroll
                for (int rr = 0; rr < 4; rr++) {
                    const long row = row0 + warp * 4 + rr;
                    const float2* xp = (const float2*)(query + row * DQ);
                    float xr[DQ];
                    #pragma unroll
                    for (int d = 0; d < 7; d++) {
                        float2 v = __ldg(&xp[d]);
                        xr[2 * d] = v.x; xr[2 * d + 1] = v.y;
                    }
                    float hj = b1r;
                    hj = fmaf(wa.x, xr[0], hj);  hj = fmaf(wa.y, xr[1], hj);
                    hj = fmaf(wa.z, xr[2], hj);  hj = fmaf(wa.w, xr[3], hj);
                    hj = fmaf(wb.x, xr[4], hj);  hj = fmaf(wb.y, xr[5], hj);
                    hj = fmaf(wb.z, xr[6], hj);  hj = fmaf(wb.w, xr[7], hj);
                    hj = fmaf(wc.x, xr[8], hj);  hj = fmaf(wc.y, xr[9], hj);
                    hj = fmaf(wc.z, xr[10], hj); hj = fmaf(wc.w, xr[11], hj);
                    hj = fmaf(wd2.x, xr[12], hj); hj = fmaf(wd2.y, xr[13], hj);
                    hj = 0.5f * hj * (1.0f + erff(hj * 0.7071067811865476f));
                    h4_s[warp * 128 + rr * 32 + lane] = hj;
                }
            }
            __syncwarp();

            // pass 2: q8, W2 fragments loaded once; store scaled fp16 q8
            {
                const int ci = lane & 7;
                const float b2r = b2_s[ci];
                float q[4] = {b2r, b2r, b2r, b2r};
                const float4* w2v = (const float4*)(smem + SO_W2R + ci * 144);
                const float4* hv  = (const float4*)(h4_s + warp * 128);
                #pragma unroll
                for (int j4 = 0; j4 < 8; j4++) {
                    const float4 w4 = w2v[j4];
                    #pragma unroll
                    for (int rr = 0; rr < 4; rr++) {
                        const float4 h4 = hv[rr * 8 + j4];
                        q[rr] = fmaf(w4.x, h4.x, q[rr]);
                        q[rr] = fmaf(w4.y, h4.y, q[rr]);
                        q[rr] = fmaf(w4.z, h4.z, q[rr]);
                        q[rr] = fmaf(w4.w, h4.w, q[rr]);
                    }
                }
                const int g = lane >> 3;    // which row this lane-group stores
                #pragma unroll
                for (int rr = 0; rr < 4; rr++) {
                    float ss = q[rr] * q[rr];
                    ss += __shfl_xor_sync(0xffffffffu, ss, 1);
                    ss += __shfl_xor_sync(0xffffffffu, ss, 2);
                    ss += __shfl_xor_sync(0xffffffffu, ss, 4);
                    // fold 1/||q|| and BETA*log2e/sqrt(2)
                    const float inv = CSCALE / fmaxf(sqrtf(ss), 1e-12f);
                    const float qn = q[rr] * inv;
                    if (g == rr)
                        sts_u16(q8_base + ((warp * 4 + rr) * 8 + ci) * 2,
                                __half_as_ushort(__float2half_rn(qn)));
                }
            }
        }
        __syncthreads();

        // ====== R2: sim GEMM (m16n8k8) + exp + e->A tile + row partials ====
        {
            const int mband = warp & 7;          // 8 bands of 16 rows
            const int nband = warp >> 3;         // 4 bands of 64 keys
            const int m0s = mband * 16;
            const int n0s = nband * 64;

            uint32_t qa0, qa1;
            ldsm_x2(qa0, qa1, q8_base + (m0s + (lane & 15)) * 16);
            uint32_t kb[8];
            ldsm_x4(kb[0], kb[1], kb[2], kb[3], k_base + (n0s + lane) * 16);
            ldsm_x4(kb[4], kb[5], kb[6], kb[7], k_base + (n0s + 32 + lane) * 16);

            float d[8][4];
            #pragma unroll
            for (int t = 0; t < 8; t++) {
                d[t][0] = d[t][1] = d[t][2] = d[t][3] = 0.f;
                mma16808(d[t], qa0, qa1, kb[t]);
            }

            // exp + store e (half2) + per-thread row partial sums
            const int rA = m0s + (lane >> 2);
            const uint32_t arow0 = a_base + rA * (AK * 2) + (n0s + (lane & 3) * 2) * 2;
            const uint32_t arow1 = arow0 + 8 * (AK * 2);
            float sL = 0.f, sH = 0.f;
            const int tmax = (nband == 3) ? 6 : 8;   // mask keys >= 240
            #pragma unroll
            for (int t = 0; t < 8; t++) {
                if (t < tmax) {
                    const float e0 = exp2_fast(d[t][0] - CLOG2E);
                    const float e1 = exp2_fast(d[t][1] - CLOG2E);
                    const float e2 = exp2_fast(d[t][2] - CLOG2E);
                    const float e3 = exp2_fast(d[t][3] - CLOG2E);
                    const __half2 h01 = __floats2half2_rn(e0, e1);
                    const __half2 h23 = __floats2half2_rn(e2, e3);
                    sts_u32(arow0 + t * 16, *(const uint32_t*)&h01);
                    sts_u32(arow1 + t * 16, *(const uint32_t*)&h23);
                    sL += e0 + e1;
                    sH += e2 + e3;
                }
            }
            sL += __shfl_xor_sync(0xffffffffu, sL, 1);
            sL += __shfl_xor_sync(0xffffffffu, sL, 2);
            sH += __shfl_xor_sync(0xffffffffu, sH, 1);
            sH += __shfl_xor_sync(0xffffffffu, sH, 2);
            if ((lane & 3) == 0) {
                rsp_s[nband * 128 + rA] = sL;
                rsp_s[nband * 128 + rA + 8] = sH;
            }
        }
        __syncthreads();

        // ====== R3: attn out + content GEMM + epilogue =====================
        {
            // ---- attn output: e * (1/rowsum) -> gmem ----
            const uint32_t a_row_base = a_base + (warp * 4) * (AK * 2);
            #pragma unroll
            for (int rr = 0; rr < 4; rr++) {
                const int r = warp * 4 + rr;
                const float rsum = rsp_s[r] + rsp_s[128 + r]
                                 + rsp_s[256 + r] + rsp_s[384 + r];
                const float invs = __fdividef(1.0f, rsum);
                float* arow = attn_out + (row0 + r) * NS;
                #pragma unroll
                for (int tp = 0; tp < 4; tp++) {
                    const int idx = lane + 32 * tp;
                    if (idx < NS / 2) {
                        const uint32_t v = lds_u32(a_row_base + rr * (AK * 2) + idx * 4);
                        const __half2 h2 = *(const __half2*)&v;
                        const float2 f = __half22float2(h2);
                        *(float2*)(arow + 2 * idx) = make_float2(f.x * invs, f.y * invs);
                    }
                }
            }

            // ---- content = A(e) @ Bn^T, 32m x 32n warp tiles ----
            const int m0 = (warp & 3) * 32;
            const int n0 = (warp >> 2) * 32;

            float acc[2][4][4];
            #pragma unroll
            for (int i = 0; i < 2; i++)
                #pragma unroll
                for (int t = 0; t < 4; t++)
                    #pragma unroll
                    for (int j = 0; j < 4; j++) acc[i][t][j] = 0.f;

            const uint32_t a_lane0 = a_base
                + ((m0 + (lane & 15)) * AK + (lane >> 4) * 8) * 2;
            const uint32_t a_lane1 = a_lane0 + 16 * AK * 2;
            const uint32_t b_lane = b_base
                + ((n0 + ((lane >> 4) << 3) + (lane & 7)) * BKS
                   + (((lane >> 3) & 1) * 8)) * 2;

            #pragma unroll
            for (int ks = 0; ks < NKSTEP; ks++) {
                uint32_t a0[4], a1[4];
                ldsm_x4(a0[0], a0[1], a0[2], a0[3], a_lane0 + ks * 32);
                ldsm_x4(a1[0], a1[1], a1[2], a1[3], a_lane1 + ks * 32);
                #pragma unroll
                for (int np = 0; np < 2; np++) {
                    uint32_t b0, b1, b2, b3;
                    ldsm_x4(b0, b1, b2, b3, b_lane + (np * 16 * BKS + ks * 16) * 2);
                    mma16816(acc[0][2 * np],     a0[0], a0[1], a0[2], a0[3], b0, b1);
                    mma16816(acc[0][2 * np + 1], a0[0], a0[1], a0[2], a0[3], b2, b3);
                    mma16816(acc[1][2 * np],     a1[0], a1[1], a1[2], a1[3], b0, b1);
                    mma16816(acc[1][2 * np + 1], a1[0], a1[1], a1[2], a1[3], b2, b3);
                }
            }

            // epilogue: scale by 1/rowsum (4 partials), store
            #pragma unroll
            for (int i = 0; i < 2; i++) {
                const int lrA = m0 + i * 16 + (lane >> 2);
                const float sA = rsp_s[lrA] + rsp_s[128 + lrA]
                               + rsp_s[256 + lrA] + rsp_s[384 + lrA];
                const int lrB = lrA + 8;
                const float sB = rsp_s[lrB] + rsp_s[128 + lrB]
                               + rsp_s[256 + lrB] + rsp_s[384 + lrB];
                const float invA = __fdividef(1.0f, sA);
                const float invB = __fdividef(1.0f, sB);
                const long r0 = row0 + lrA;
                const int cofs = (lane & 3) * 2;
                #pragma unroll
                for (int t = 0; t < 4; t++) {
                    const int col = n0 + t * 8 + cofs;
                    *(float2*)(content + r0 * DV + col) =
                        make_float2(acc[i][t][0] * invA, acc[i][t][1] * invA);
                    *(float2*)(content + (r0 + 8) * DV + col) =
                        make_float2(acc[i][t][2] * invB, acc[i][t][3] * invB);
                }
            }
        }
        __syncthreads();   // A_s / q8s / rsp fully consumed before next tile
    }
}

// ---------------------------------------------------------------------------
extern "C" void kernel_launch(void* const* d_in, const int* in_sizes, int n_in,
                              void* d_out, int out_size)
{
    const float* query  = (const float*)d_in[0];
    const float* W1     = (const float*)d_in[1];
    const float* b1     = (const float*)d_in[2];
    const float* W2     = (const float*)d_in[3];
    const float* b2     = (const float*)d_in[4];
    const float* values = (const float*)d_in[5];
    const float* keys   = (const float*)d_in[6];

    const int nrows  = in_sizes[0] / DQ;   // 262144
    const int ntiles = (nrows + TILE_M - 1) / TILE_M;

    float* out = (float*)d_out;
    float* content = out;
    float* attn;
    float* scratch;
    cudaGetSymbolAddress((void**)&scratch, g_attn_scratch);
    if ((long)out_size >= (long)nrows * (DV + NS)) {
        attn = out + (long)nrows * DV;
    } else {
        attn = scratch;
    }

    cudaFuncSetAttribute(fused_kernel, cudaFuncAttributeMaxDynamicSharedMemorySize,
                         SMEM_TOTAL);

    fused_kernel<<<152, NTHREADS, SMEM_TOTAL>>>(
        query, W1, b1, W2, b2, values, keys, content, attn, nrows, ntiles);
}

// round 14
// speedup vs baseline: 1.2610x; 1.0674x over previous
#include <cuda_runtime.h>
#include <cuda_fp16.h>
#include <math.h>
#include <stdint.h>

#define DQ 14
#define HID 32
#define DK 8
#define NS 240
#define DV 256
#define NTHREADS 1024
#define TILE_M 128
#define NKSTEP 15          // 240 / 16
#define AK 248             // A smem row stride in halves (496 B)
#define BKS 248            // B smem row stride in halves (496 B)

// ---- smem layout (bytes) ----
#define SO_W1P    0            // float[32][20] (pad, 14 used)
#define SO_B1     2560         // float[32]
#define SO_W2R    2688         // float[8][36]  (pad, 32 used)
#define SO_B2     3840         // float[8]
#define SO_KEYH   3872         // half[256][8] exact sqrt2-scaled keys = 4096
#define SO_H4     7968         // float[32][4][32] = 16384
#define SO_Q8S    24352        // 2 x half[128][8] scaled q8 (double buf) = 4096
#define SO_RSP    28448        // float[4][128] partial row sums = 2048
#define SO_A      30496        // half[128][AK] = 63488 (unnormalized e)
#define SO_B      93984        // half[256][BKS] = 126976 (values, n-major)
#define SMEM_TOTAL 220960

#define BETA 2.0f
#define CLOG2E 2.88539008177792681f        // BETA * log2(e)
#define CSCALE 2.04027885f                 // BETA * log2(e) / sqrt(2)

__device__ float g_attn_scratch[262144 * NS];

// ---------------------------------------------------------------------------
__device__ __forceinline__ uint32_t smem_u32(const void* p) {
    uint32_t a;
    asm("{ .reg .u64 t; cvta.to.shared.u64 t, %1; cvt.u32.u64 %0, t; }" : "=r"(a) : "l"(p));
    return a;
}
__device__ __forceinline__ void ldsm_x2(uint32_t& r0, uint32_t& r1, uint32_t addr) {
    asm volatile("ldmatrix.sync.aligned.m8n8.x2.shared.b16 {%0,%1}, [%2];"
                 : "=r"(r0), "=r"(r1) : "r"(addr));
}
__device__ __forceinline__ void ldsm_x4(uint32_t& r0, uint32_t& r1, uint32_t& r2, uint32_t& r3,
                                        uint32_t addr) {
    asm volatile("ldmatrix.sync.aligned.m8n8.x4.shared.b16 {%0,%1,%2,%3}, [%4];"
                 : "=r"(r0), "=r"(r1), "=r"(r2), "=r"(r3) : "r"(addr));
}
__device__ __forceinline__ void mma16816(float* d, uint32_t a0, uint32_t a1, uint32_t a2,
                                         uint32_t a3, uint32_t b0, uint32_t b1) {
    asm volatile(
        "mma.sync.aligned.m16n8k16.row.col.f32.f16.f16.f32 "
        "{%0,%1,%2,%3}, {%4,%5,%6,%7}, {%8,%9}, {%0,%1,%2,%3};"
        : "+f"(d[0]), "+f"(d[1]), "+f"(d[2]), "+f"(d[3])
        : "r"(a0), "r"(a1), "r"(a2), "r"(a3), "r"(b0), "r"(b1));
}
__device__ __forceinline__ void mma16808(float* d, uint32_t a0, uint32_t a1, uint32_t b0) {
    asm volatile(
        "mma.sync.aligned.m16n8k8.row.col.f32.f16.f16.f32 "
        "{%0,%1,%2,%3}, {%4,%5}, {%6}, {%0,%1,%2,%3};"
        : "+f"(d[0]), "+f"(d[1]), "+f"(d[2]), "+f"(d[3])
        : "r"(a0), "r"(a1), "r"(b0));
}
__device__ __forceinline__ void sts_u16(uint32_t addr, unsigned short v) {
    asm volatile("st.shared.u16 [%0], %1;" :: "r"(addr), "h"(v) : "memory");
}
__device__ __forceinline__ void sts_u32(uint32_t addr, uint32_t v) {
    asm volatile("st.shared.u32 [%0], %1;" :: "r"(addr), "r"(v) : "memory");
}
__device__ __forceinline__ uint32_t lds_u32(uint32_t addr) {
    uint32_t v;
    asm volatile("ld.shared.u32 %0, [%1];" : "=r"(v) : "r"(addr));
    return v;
}

// Fast 2^y: magic-constant round + deg-5 poly + exponent patch (no MUFU).
__device__ __forceinline__ float exp2_fast(float y) {
    const float magic = 12582912.0f;          // 2^23 + 2^22
    const float t = y + magic;
    const int   j = __float_as_int(t);
    const float f = y - (t - magic);          // f in [-0.5, 0.5]
    float p = 0.00133335581f;
    p = fmaf(p, f, 0.00961812911f);
    p = fmaf(p, f, 0.05550410866f);
    p = fmaf(p, f, 0.24022650696f);
    p = fmaf(p, f, 0.69314718056f);
    p = fmaf(p, f, 1.0f);
    return __int_as_float(__float_as_int(p) + (j << 23));
}

// ---------------------------------------------------------------------------
// R1: projection (14 -> 32 GELU -> 8, normalize+scale) -> fp16 q8 in smem buf
// ---------------------------------------------------------------------------
__device__ __forceinline__ void regionR1(
    const float* __restrict__ query, char* smem, uint32_t q8buf,
    int warp, int lane, long row0)
{
    float* h4_s = (float*)(smem + SO_H4);

    // pass 1: hidden layer for 4 rows
    {
        const float4* w1v = (const float4*)(smem + SO_W1P + lane * 80);
        const float4 wa = w1v[0], wb = w1v[1], wc = w1v[2], wd2 = w1v[3];
        const float b1r = ((const float*)(smem + SO_B1))[lane];
        #pragma unroll
        for (int rr = 0; rr < 4; rr++) {
            const long row = row0 + warp * 4 + rr;
            const float2* xp = (const float2*)(query + row * DQ);
            float xr[DQ];
            #pragma unroll
            for (int d = 0; d < 7; d++) {
                float2 v = __ldg(&xp[d]);
                xr[2 * d] = v.x; xr[2 * d + 1] = v.y;
            }
            float hj = b1r;
            hj = fmaf(wa.x, xr[0], hj);  hj = fmaf(wa.y, xr[1], hj);
            hj = fmaf(wa.z, xr[2], hj);  hj = fmaf(wa.w, xr[3], hj);
            hj = fmaf(wb.x, xr[4], hj);  hj = fmaf(wb.y, xr[5], hj);
            hj = fmaf(wb.z, xr[6], hj);  hj = fmaf(wb.w, xr[7], hj);
            hj = fmaf(wc.x, xr[8], hj);  hj = fmaf(wc.y, xr[9], hj);
            hj = fmaf(wc.z, xr[10], hj); hj = fmaf(wc.w, xr[11], hj);
            hj = fmaf(wd2.x, xr[12], hj); hj = fmaf(wd2.y, xr[13], hj);
            hj = 0.5f * hj * (1.0f + erff(hj * 0.7071067811865476f));
            h4_s[warp * 128 + rr * 32 + lane] = hj;
        }
    }
    __syncwarp();

    // pass 2: q8, W2 fragments loaded once; store scaled fp16 q8
    {
        const int ci = lane & 7;
        const float b2r = ((const float*)(smem + SO_B2))[ci];
        float q[4] = {b2r, b2r, b2r, b2r};
        const float4* w2v = (const float4*)(smem + SO_W2R + ci * 144);
        const float4* hv  = (const float4*)(h4_s + warp * 128);
        #pragma unroll
        for (int j4 = 0; j4 < 8; j4++) {
            const float4 w4 = w2v[j4];
            #pragma unroll
            for (int rr = 0; rr < 4; rr++) {
                const float4 h4 = hv[rr * 8 + j4];
                q[rr] = fmaf(w4.x, h4.x, q[rr]);
                q[rr] = fmaf(w4.y, h4.y, q[rr]);
                q[rr] = fmaf(w4.z, h4.z, q[rr]);
                q[rr] = fmaf(w4.w, h4.w, q[rr]);
            }
        }
        const int g = lane >> 3;
        #pragma unroll
        for (int rr = 0; rr < 4; rr++) {
            float ss = q[rr] * q[rr];
            ss += __shfl_xor_sync(0xffffffffu, ss, 1);
            ss += __shfl_xor_sync(0xffffffffu, ss, 2);
            ss += __shfl_xor_sync(0xffffffffu, ss, 4);
            const float inv = CSCALE / fmaxf(sqrtf(ss), 1e-12f);
            const float qn = q[rr] * inv;
            if (g == rr)
                sts_u16(q8buf + ((warp * 4 + rr) * 8 + ci) * 2,
                        __half_as_ushort(__float2half_rn(qn)));
        }
    }
}

// ---------------------------------------------------------------------------
// R3: attn out + content GEMM + epilogue
// ---------------------------------------------------------------------------
__device__ __forceinline__ void regionR3(
    float* __restrict__ content, float* __restrict__ attn_out,
    uint32_t a_base, uint32_t b_base, const float* rsp_s,
    int warp, int lane, long row0)
{
    // ---- attn output: e * (1/rowsum) -> gmem ----
    const uint32_t a_row_base = a_base + (warp * 4) * (AK * 2);
    #pragma unroll
    for (int rr = 0; rr < 4; rr++) {
        const int r = warp * 4 + rr;
        const float rsum = rsp_s[r] + rsp_s[128 + r]
                         + rsp_s[256 + r] + rsp_s[384 + r];
        const float invs = __fdividef(1.0f, rsum);
        float* arow = attn_out + (row0 + r) * NS;
        #pragma unroll
        for (int tp = 0; tp < 4; tp++) {
            const int idx = lane + 32 * tp;
            if (idx < NS / 2) {
                const uint32_t v = lds_u32(a_row_base + rr * (AK * 2) + idx * 4);
                const __half2 h2 = *(const __half2*)&v;
                const float2 f = __half22float2(h2);
                *(float2*)(arow + 2 * idx) = make_float2(f.x * invs, f.y * invs);
            }
        }
    }

    // ---- content = A(e) @ Bn^T, 32m x 32n warp tiles ----
    const int m0 = (warp & 3) * 32;
    const int n0 = (warp >> 2) * 32;

    float acc[2][4][4];
    #pragma unroll
    for (int i = 0; i < 2; i++)
        #pragma unroll
        for (int t = 0; t < 4; t++)
            #pragma unroll
            for (int j = 0; j < 4; j++) acc[i][t][j] = 0.f;

    const uint32_t a_lane0 = a_base
        + ((m0 + (lane & 15)) * AK + (lane >> 4) * 8) * 2;
    const uint32_t a_lane1 = a_lane0 + 16 * AK * 2;
    const uint32_t b_lane = b_base
        + ((n0 + ((lane >> 4) << 3) + (lane & 7)) * BKS
           + (((lane >> 3) & 1) * 8)) * 2;

    #pragma unroll
    for (int ks = 0; ks < NKSTEP; ks++) {
        uint32_t a0[4], a1[4];
        ldsm_x4(a0[0], a0[1], a0[2], a0[3], a_lane0 + ks * 32);
        ldsm_x4(a1[0], a1[1], a1[2], a1[3], a_lane1 + ks * 32);
        #pragma unroll
        for (int np = 0; np < 2; np++) {
            uint32_t b0, b1, b2, b3;
            ldsm_x4(b0, b1, b2, b3, b_lane + (np * 16 * BKS + ks * 16) * 2);
            mma16816(acc[0][2 * np],     a0[0], a0[1], a0[2], a0[3], b0, b1);
            mma16816(acc[0][2 * np + 1], a0[0], a0[1], a0[2], a0[3], b2, b3);
            mma16816(acc[1][2 * np],     a1[0], a1[1], a1[2], a1[3], b0, b1);
            mma16816(acc[1][2 * np + 1], a1[0], a1[1], a1[2], a1[3], b2, b3);
        }
    }

    // epilogue: scale by 1/rowsum (4 partials), store
    #pragma unroll
    for (int i = 0; i < 2; i++) {
        const int lrA = m0 + i * 16 + (lane >> 2);
        const float sA = rsp_s[lrA] + rsp_s[128 + lrA]
                       + rsp_s[256 + lrA] + rsp_s[384 + lrA];
        const int lrB = lrA + 8;
        const float sB = rsp_s[lrB] + rsp_s[128 + lrB]
                       + rsp_s[256 + lrB] + rsp_s[384 + lrB];
        const float invA = __fdividef(1.0f, sA);
        const float invB = __fdividef(1.0f, sB);
        const long r0 = row0 + lrA;
        const int cofs = (lane & 3) * 2;
        #pragma unroll
        for (int t = 0; t < 4; t++) {
            const int col = n0 + t * 8 + cofs;
            *(float2*)(content + r0 * DV + col) =
                make_float2(acc[i][t][0] * invA, acc[i][t][1] * invA);
            *(float2*)(content + (r0 + 8) * DV + col) =
                make_float2(acc[i][t][2] * invB, acc[i][t][3] * invB);
        }
    }
}

// ---------------------------------------------------------------------------
__global__ __launch_bounds__(NTHREADS, 1) void fused_kernel(
    const float* __restrict__ query,
    const float* __restrict__ W1, const float* __restrict__ b1,
    const float* __restrict__ W2, const float* __restrict__ b2,
    const float* __restrict__ values,
    const float* __restrict__ keys,
    float* __restrict__ content,
    float* __restrict__ attn_out,
    int nrows, int ntiles)
{
    extern __shared__ char smem[];
    float* rsp_s  = (float*)(smem + SO_RSP);

    const uint32_t smem_base = smem_u32(smem);
    const uint32_t a_base  = smem_base + SO_A;
    const uint32_t b_base  = smem_base + SO_B;
    const uint32_t k_base  = smem_base + SO_KEYH;
    const uint32_t q8_base = smem_base + SO_Q8S;

    const int tid  = threadIdx.x;
    const int warp = tid >> 5;
    const int lane = tid & 31;

    // ---- one-time setup ----
    {
        float* W1p = (float*)(smem + SO_W1P);
        for (int i = tid; i < HID * 20; i += NTHREADS) {
            int r = i / 20, d = i % 20;
            W1p[i] = (d < DQ) ? W1[r * DQ + d] : 0.f;
        }
        float* B1s = (float*)(smem + SO_B1);
        for (int i = tid; i < HID; i += NTHREADS) B1s[i] = b1[i];
        float* W2r = (float*)(smem + SO_W2R);
        for (int i = tid; i < DK * 36; i += NTHREADS) {
            int r = i / 36, j = i % 36;
            W2r[i] = (j < HID) ? W2[r * HID + j] : 0.f;
        }
        float* B2s = (float*)(smem + SO_B2);
        for (int i = tid; i < DK; i += NTHREADS) B2s[i] = b2[i];
        // exact fp16 keys: keys_n * sqrt(2) = E8 roots, components {0,+-1,+-0.5}
        for (int i = tid; i < 256 * DK; i += NTHREADS) {
            int k = i / DK, c = i % DK;
            float v = (k < NS) ? keys[k * DK + c] * 1.41421356237f : 0.f;
            sts_u16(k_base + i * 2, __half_as_ushort(__float2half_rn(v)));
        }
        // Bn[n][k] fp16 (n-major transpose of values[k][n])
        for (int i = tid; i < NS * (DV / 2); i += NTHREADS) {
            const int k  = i / (DV / 2);
            const int np = i % (DV / 2);
            const float2 v = __ldg((const float2*)(values + k * DV + 2 * np));
            sts_u16(b_base + ((2 * np)     * BKS + k) * 2,
                    __half_as_ushort(__float2half_rn(v.x)));
            sts_u16(b_base + ((2 * np + 1) * BKS + k) * 2,
                    __half_as_ushort(__float2half_rn(v.y)));
        }
    }
    __syncthreads();

    // ---- prologue: R1 of this CTA's first tile into q8 buf 0 ----
    regionR1(query, smem, q8_base, warp, lane, (long)blockIdx.x * TILE_M);
    __syncthreads();

    int i = 0;
    for (long t = blockIdx.x; t < ntiles; t += gridDim.x, i++) {
        const long row0 = t * TILE_M;
        const uint32_t q8cur = q8_base + (i & 1) * 2048;
        const uint32_t q8nxt = q8_base + ((i & 1) ^ 1) * 2048;

        // ====== R2: sim GEMM (m16n8k8) + exp + e->A tile + row partials ====
        {
            const int mband = warp & 7;          // 8 bands of 16 rows
            const int nband = warp >> 3;         // 4 bands of 64 keys
            const int m0s = mband * 16;
            const int n0s = nband * 64;

            uint32_t qa0, qa1;
            ldsm_x2(qa0, qa1, q8cur + (m0s + (lane & 15)) * 16);
            uint32_t kb[8];
            ldsm_x4(kb[0], kb[1], kb[2], kb[3], k_base + (n0s + lane) * 16);
            ldsm_x4(kb[4], kb[5], kb[6], kb[7], k_base + (n0s + 32 + lane) * 16);

            float d[8][4];
            #pragma unroll
            for (int tt = 0; tt < 8; tt++) {
                d[tt][0] = d[tt][1] = d[tt][2] = d[tt][3] = 0.f;
                mma16808(d[tt], qa0, qa1, kb[tt]);
            }

            const int rA = m0s + (lane >> 2);
            const uint32_t arow0 = a_base + rA * (AK * 2) + (n0s + (lane & 3) * 2) * 2;
            const uint32_t arow1 = arow0 + 8 * (AK * 2);
            float sL = 0.f, sH = 0.f;
            const int tmax = (nband == 3) ? 6 : 8;   // mask keys >= 240
            #pragma unroll
            for (int tt = 0; tt < 8; tt++) {
                if (tt < tmax) {
                    const float e0 = exp2_fast(d[tt][0] - CLOG2E);
                    const float e1 = exp2_fast(d[tt][1] - CLOG2E);
                    const float e2 = exp2_fast(d[tt][2] - CLOG2E);
                    const float e3 = exp2_fast(d[tt][3] - CLOG2E);
                    const __half2 h01 = __floats2half2_rn(e0, e1);
                    const __half2 h23 = __floats2half2_rn(e2, e3);
                    sts_u32(arow0 + tt * 16, *(const uint32_t*)&h01);
                    sts_u32(arow1 + tt * 16, *(const uint32_t*)&h23);
                    sL += e0 + e1;
                    sH += e2 + e3;
                }
            }
            sL += __shfl_xor_sync(0xffffffffu, sL, 1);
            sL += __shfl_xor_sync(0xffffffffu, sL, 2);
            sH += __shfl_xor_sync(0xffffffffu, sH, 1);
            sH += __shfl_xor_sync(0xffffffffu, sH, 2);
            if ((lane & 3) == 0) {
                rsp_s[nband * 128 + rA] = sL;
                rsp_s[nband * 128 + rA + 8] = sH;
            }
        }
        __syncthreads();

        // ====== merged region: R3(t) and R1(t+grid), order alternating ====
        const long nt = t + gridDim.x;
        if (warp & 1) {
            if (nt < ntiles)
                regionR1(query, smem, q8nxt, warp, lane, nt * TILE_M);
            regionR3(content, attn_out, a_base, b_base, rsp_s, warp, lane, row0);
        } else {
            regionR3(content, attn_out, a_base, b_base, rsp_s, warp, lane, row0);
            if (nt < ntiles)
                regionR1(query, smem, q8nxt, warp, lane, nt * TILE_M);
        }
        __syncthreads();
    }
}

// ---------------------------------------------------------------------------
extern "C" void kernel_launch(void* const* d_in, const int* in_sizes, int n_in,
                              void* d_out, int out_size)
{
    const float* query  = (const float*)d_in[0];
    const float* W1     = (const float*)d_in[1];
    const float* b1     = (const float*)d_in[2];
    const float* W2     = (const float*)d_in[3];
    const float* b2     = (const float*)d_in[4];
    const float* values = (const float*)d_in[5];
    const float* keys   = (const float*)d_in[6];

    const int nrows  = in_sizes[0] / DQ;   // 262144
    const int ntiles = (nrows + TILE_M - 1) / TILE_M;

    float* out = (float*)d_out;
    float* content = out;
    float* attn;
    float* scratch;
    cudaGetSymbolAddress((void**)&scratch, g_attn_scratch);
    if ((long)out_size >= (long)nrows * (DV + NS)) {
        attn = out + (long)nrows * DV;
    } else {
        attn = scratch;
    }

    cudaFuncSetAttribute(fused_kernel, cudaFuncAttributeMaxDynamicSharedMemorySize,
                         SMEM_TOTAL);

    fused_kernel<<<152, NTHREADS, SMEM_TOTAL>>>(
        query, W1, b1, W2, b2, values, keys, content, attn, nrows, ntiles);
}

// round 16
// speedup vs baseline: 1.2957x; 1.0275x over previous
#include <cuda_runtime.h>
#include <cuda_fp16.h>
#include <math.h>
#include <stdint.h>

#define DQ 14
#define HID 32
#define DK 8
#define NS 240
#define DV 256
#define NTHREADS 512
#define TILE_M 128
#define NKSTEP 15          // 240 / 16
#define AK 248             // A smem row stride in halves (496 B)
#define BKS 248            // B smem row stride in halves (496 B)

// ---- smem layout (bytes) ----
#define SO_W1P    0            // float[32][20] (pad, 14 used)
#define SO_B1     2560         // float[32]
#define SO_W2R    2688         // float[8][36]  (pad, 32 used)
#define SO_B2     3840         // float[8]
#define SO_KEYH   3872         // half[256][8] exact sqrt2-scaled keys = 4096
#define SO_H4     7968         // float[16][4][32] = 8192
#define SO_Q8S    16160        // 2 x half[128][8] scaled q8 (double buf) = 4096
#define SO_RSP    20256        // float[4][128] partial row sums = 2048
#define SO_A      22304        // half[128][AK] = 63488 (unnormalized e)
#define SO_B      85792        // half[256][BKS] = 126976 (values, n-major)
#define SMEM_TOTAL 212768

#define BETA 2.0f
#define CLOG2E 2.88539008177792681f        // BETA * log2(e)
#define CSCALE 2.04027885f                 // BETA * log2(e) / sqrt(2)

__device__ float g_attn_scratch[262144 * NS];

// ---------------------------------------------------------------------------
__device__ __forceinline__ uint32_t smem_u32(const void* p) {
    uint32_t a;
    asm("{ .reg .u64 t; cvta.to.shared.u64 t, %1; cvt.u32.u64 %0, t; }" : "=r"(a) : "l"(p));
    return a;
}
__device__ __forceinline__ void ldsm_x2(uint32_t& r0, uint32_t& r1, uint32_t addr) {
    asm volatile("ldmatrix.sync.aligned.m8n8.x2.shared.b16 {%0,%1}, [%2];"
                 : "=r"(r0), "=r"(r1) : "r"(addr));
}
__device__ __forceinline__ void ldsm_x4(uint32_t& r0, uint32_t& r1, uint32_t& r2, uint32_t& r3,
                                        uint32_t addr) {
    asm volatile("ldmatrix.sync.aligned.m8n8.x4.shared.b16 {%0,%1,%2,%3}, [%4];"
                 : "=r"(r0), "=r"(r1), "=r"(r2), "=r"(r3) : "r"(addr));
}
__device__ __forceinline__ void mma16816(float* d, uint32_t a0, uint32_t a1, uint32_t a2,
                                         uint32_t a3, uint32_t b0, uint32_t b1) {
    asm volatile(
        "mma.sync.aligned.m16n8k16.row.col.f32.f16.f16.f32 "
        "{%0,%1,%2,%3}, {%4,%5,%6,%7}, {%8,%9}, {%0,%1,%2,%3};"
        : "+f"(d[0]), "+f"(d[1]), "+f"(d[2]), "+f"(d[3])
        : "r"(a0), "r"(a1), "r"(a2), "r"(a3), "r"(b0), "r"(b1));
}
__device__ __forceinline__ void mma16808(float* d, uint32_t a0, uint32_t a1, uint32_t b0) {
    asm volatile(
        "mma.sync.aligned.m16n8k8.row.col.f32.f16.f16.f32 "
        "{%0,%1,%2,%3}, {%4,%5}, {%6}, {%0,%1,%2,%3};"
        : "+f"(d[0]), "+f"(d[1]), "+f"(d[2]), "+f"(d[3])
        : "r"(a0), "r"(a1), "r"(b0));
}
__device__ __forceinline__ void sts_u16(uint32_t addr, unsigned short v) {
    asm volatile("st.shared.u16 [%0], %1;" :: "r"(addr), "h"(v) : "memory");
}
__device__ __forceinline__ void sts_u32(uint32_t addr, uint32_t v) {
    asm volatile("st.shared.u32 [%0], %1;" :: "r"(addr), "r"(v) : "memory");
}
__device__ __forceinline__ uint32_t lds_u32(uint32_t addr) {
    uint32_t v;
    asm volatile("ld.shared.u32 %0, [%1];" : "=r"(v) : "r"(addr));
    return v;
}

// Fast 2^y: magic-constant round + deg-5 poly + exponent patch (no MUFU).
__device__ __forceinline__ float exp2_fast(float y) {
    const float magic = 12582912.0f;          // 2^23 + 2^22
    const float t = y + magic;
    const int   j = __float_as_int(t);
    const float f = y - (t - magic);          // f in [-0.5, 0.5]
    float p = 0.00133335581f;
    p = fmaf(p, f, 0.00961812911f);
    p = fmaf(p, f, 0.05550410866f);
    p = fmaf(p, f, 0.24022650696f);
    p = fmaf(p, f, 0.69314718056f);
    p = fmaf(p, f, 1.0f);
    return __int_as_float(__float_as_int(p) + (j << 23));
}

// ---------------------------------------------------------------------------
// R1: projection for 8 rows/warp -> scaled fp16 q8 into q8buf
// ---------------------------------------------------------------------------
__device__ __forceinline__ void regionR1(
    const float* __restrict__ query, char* smem, uint32_t q8buf,
    int warp, int lane, long row0)
{
    float* h4_s = (float*)(smem + SO_H4);
    const float4* w1v = (const float4*)(smem + SO_W1P + lane * 80);
    const float4 wa = w1v[0], wb = w1v[1], wc = w1v[2], wd2 = w1v[3];
    const float b1r = ((const float*)(smem + SO_B1))[lane];
    const int ci = lane & 7;
    const float b2r = ((const float*)(smem + SO_B2))[ci];
    const float4* w2v = (const float4*)(smem + SO_W2R + ci * 144);
    const float4* hv  = (const float4*)(h4_s + warp * 128);
    const int g = lane >> 3;

    #pragma unroll
    for (int g2 = 0; g2 < 2; g2++) {
        // pass 1: hidden layer for 4 rows
        #pragma unroll
        for (int rr = 0; rr < 4; rr++) {
            const long row = row0 + warp * 8 + g2 * 4 + rr;
            const float2* xp = (const float2*)(query + row * DQ);
            float xr[DQ];
            #pragma unroll
            for (int d = 0; d < 7; d++) {
                float2 v = __ldg(&xp[d]);
                xr[2 * d] = v.x; xr[2 * d + 1] = v.y;
            }
            float hj = b1r;
            hj = fmaf(wa.x, xr[0], hj);  hj = fmaf(wa.y, xr[1], hj);
            hj = fmaf(wa.z, xr[2], hj);  hj = fmaf(wa.w, xr[3], hj);
            hj = fmaf(wb.x, xr[4], hj);  hj = fmaf(wb.y, xr[5], hj);
            hj = fmaf(wb.z, xr[6], hj);  hj = fmaf(wb.w, xr[7], hj);
            hj = fmaf(wc.x, xr[8], hj);  hj = fmaf(wc.y, xr[9], hj);
            hj = fmaf(wc.z, xr[10], hj); hj = fmaf(wc.w, xr[11], hj);
            hj = fmaf(wd2.x, xr[12], hj); hj = fmaf(wd2.y, xr[13], hj);
            hj = 0.5f * hj * (1.0f + erff(hj * 0.7071067811865476f));
            h4_s[warp * 128 + rr * 32 + lane] = hj;
        }
        __syncwarp();

        // pass 2: q8, W2 fragments loaded once; store scaled fp16 q8
        {
            float q[4] = {b2r, b2r, b2r, b2r};
            #pragma unroll
            for (int j4 = 0; j4 < 8; j4++) {
                const float4 w4 = w2v[j4];
                #pragma unroll
                for (int rr = 0; rr < 4; rr++) {
                    const float4 h4 = hv[rr * 8 + j4];
                    q[rr] = fmaf(w4.x, h4.x, q[rr]);
                    q[rr] = fmaf(w4.y, h4.y, q[rr]);
                    q[rr] = fmaf(w4.z, h4.z, q[rr]);
                    q[rr] = fmaf(w4.w, h4.w, q[rr]);
                }
            }
            #pragma unroll
            for (int rr = 0; rr < 4; rr++) {
                float ss = q[rr] * q[rr];
                ss += __shfl_xor_sync(0xffffffffu, ss, 1);
                ss += __shfl_xor_sync(0xffffffffu, ss, 2);
                ss += __shfl_xor_sync(0xffffffffu, ss, 4);
                const float inv = CSCALE / fmaxf(sqrtf(ss), 1e-12f);
                const float qn = q[rr] * inv;
                if (g == rr)
                    sts_u16(q8buf + ((warp * 8 + g2 * 4 + rr) * 8 + ci) * 2,
                            __half_as_ushort(__float2half_rn(qn)));
            }
        }
        __syncwarp();
    }
}

// ---------------------------------------------------------------------------
// R3: attn out + content GEMM (32m x 64n warp tiles) + epilogue
// ---------------------------------------------------------------------------
__device__ __forceinline__ void regionR3(
    float* __restrict__ content, float* __restrict__ attn_out,
    uint32_t a_base, uint32_t b_base, const float* rsp_s,
    int warp, int lane, long row0)
{
    // ---- attn output: e * (1/rowsum) -> gmem (8 rows/warp) ----
    const uint32_t a_row_base = a_base + (warp * 8) * (AK * 2);
    #pragma unroll
    for (int rr = 0; rr < 8; rr++) {
        const int r = warp * 8 + rr;
        const float rsum = rsp_s[r] + rsp_s[128 + r]
                         + rsp_s[256 + r] + rsp_s[384 + r];
        const float invs = __fdividef(1.0f, rsum);
        float* arow = attn_out + (row0 + r) * NS;
        #pragma unroll
        for (int tp = 0; tp < 4; tp++) {
            const int idx = lane + 32 * tp;
            if (idx < NS / 2) {
                const uint32_t v = lds_u32(a_row_base + rr * (AK * 2) + idx * 4);
                const __half2 h2 = *(const __half2*)&v;
                const float2 f = __half22float2(h2);
                *(float2*)(arow + 2 * idx) = make_float2(f.x * invs, f.y * invs);
            }
        }
    }

    // ---- content = A(e) @ Bn^T, 32m x 64n warp tiles ----
    const int m0 = (warp & 3) * 32;
    const int n0 = (warp >> 2) * 64;

    float acc[2][8][4];
    #pragma unroll
    for (int i = 0; i < 2; i++)
        #pragma unroll
        for (int t = 0; t < 8; t++)
            #pragma unroll
            for (int j = 0; j < 4; j++) acc[i][t][j] = 0.f;

    const uint32_t a_lane0 = a_base
        + ((m0 + (lane & 15)) * AK + (lane >> 4) * 8) * 2;
    const uint32_t a_lane1 = a_lane0 + 16 * AK * 2;
    const uint32_t b_lane = b_base
        + ((n0 + ((lane >> 4) << 3) + (lane & 7)) * BKS
           + (((lane >> 3) & 1) * 8)) * 2;

    #pragma unroll
    for (int ks = 0; ks < NKSTEP; ks++) {
        uint32_t a0[4], a1[4];
        ldsm_x4(a0[0], a0[1], a0[2], a0[3], a_lane0 + ks * 32);
        ldsm_x4(a1[0], a1[1], a1[2], a1[3], a_lane1 + ks * 32);
        #pragma unroll
        for (int np = 0; np < 4; np++) {
            uint32_t b0, b1, b2, b3;
            ldsm_x4(b0, b1, b2, b3, b_lane + (np * 16 * BKS + ks * 16) * 2);
            mma16816(acc[0][2 * np],     a0[0], a0[1], a0[2], a0[3], b0, b1);
            mma16816(acc[0][2 * np + 1], a0[0], a0[1], a0[2], a0[3], b2, b3);
            mma16816(acc[1][2 * np],     a1[0], a1[1], a1[2], a1[3], b0, b1);
            mma16816(acc[1][2 * np + 1], a1[0], a1[1], a1[2], a1[3], b2, b3);
        }
    }

    // epilogue: scale by 1/rowsum (4 partials), store
    #pragma unroll
    for (int i = 0; i < 2; i++) {
        const int lrA = m0 + i * 16 + (lane >> 2);
        const float sA = rsp_s[lrA] + rsp_s[128 + lrA]
                       + rsp_s[256 + lrA] + rsp_s[384 + lrA];
        const int lrB = lrA + 8;
        const float sB = rsp_s[lrB] + rsp_s[128 + lrB]
                       + rsp_s[256 + lrB] + rsp_s[384 + lrB];
        const float invA = __fdividef(1.0f, sA);
        const float invB = __fdividef(1.0f, sB);
        const long r0 = row0 + lrA;
        const int cofs = (lane & 3) * 2;
        #pragma unroll
        for (int t = 0; t < 8; t++) {
            const int col = n0 + t * 8 + cofs;
            *(float2*)(content + r0 * DV + col) =
                make_float2(acc[i][t][0] * invA, acc[i][t][1] * invA);
            *(float2*)(content + (r0 + 8) * DV + col) =
                make_float2(acc[i][t][2] * invB, acc[i][t][3] * invB);
        }
    }
}

// ---------------------------------------------------------------------------
__global__ __launch_bounds__(NTHREADS, 1) void fused_kernel(
    const float* __restrict__ query,
    const float* __restrict__ W1, const float* __restrict__ b1,
    const float* __restrict__ W2, const float* __restrict__ b2,
    const float* __restrict__ values,
    const float* __restrict__ keys,
    float* __restrict__ content,
    float* __restrict__ attn_out,
    int nrows, int ntiles)
{
    extern __shared__ char smem[];
    float* rsp_s  = (float*)(smem + SO_RSP);

    const uint32_t smem_base = smem_u32(smem);
    const uint32_t a_base  = smem_base + SO_A;
    const uint32_t b_base  = smem_base + SO_B;
    const uint32_t k_base  = smem_base + SO_KEYH;
    const uint32_t q8_base = smem_base + SO_Q8S;

    const int tid  = threadIdx.x;
    const int warp = tid >> 5;
    const int lane = tid & 31;

    // ---- one-time setup ----
    {
        float* W1p = (float*)(smem + SO_W1P);
        for (int i = tid; i < HID * 20; i += NTHREADS) {
            int r = i / 20, d = i % 20;
            W1p[i] = (d < DQ) ? W1[r * DQ + d] : 0.f;
        }
        float* B1s = (float*)(smem + SO_B1);
        for (int i = tid; i < HID; i += NTHREADS) B1s[i] = b1[i];
        float* W2r = (float*)(smem + SO_W2R);
        for (int i = tid; i < DK * 36; i += NTHREADS) {
            int r = i / 36, j = i % 36;
            W2r[i] = (j < HID) ? W2[r * HID + j] : 0.f;
        }
        float* B2s = (float*)(smem + SO_B2);
        for (int i = tid; i < DK; i += NTHREADS) B2s[i] = b2[i];
        // exact fp16 keys: keys_n * sqrt(2) = E8 roots, components {0,+-1,+-0.5}
        for (int i = tid; i < 256 * DK; i += NTHREADS) {
            int k = i / DK, c = i % DK;
            float v = (k < NS) ? keys[k * DK + c] * 1.41421356237f : 0.f;
            sts_u16(k_base + i * 2, __half_as_ushort(__float2half_rn(v)));
        }
        // Bn[n][k] fp16 (n-major transpose of values[k][n])
        for (int i = tid; i < NS * (DV / 2); i += NTHREADS) {
            const int k  = i / (DV / 2);
            const int np = i % (DV / 2);
            const float2 v = __ldg((const float2*)(values + k * DV + 2 * np));
            sts_u16(b_base + ((2 * np)     * BKS + k) * 2,
                    __half_as_ushort(__float2half_rn(v.x)));
            sts_u16(b_base + ((2 * np + 1) * BKS + k) * 2,
                    __half_as_ushort(__float2half_rn(v.y)));
        }
    }
    __syncthreads();

    // ---- prologue: R1 of this CTA's first tile into q8 buf 0 ----
    regionR1(query, smem, q8_base, warp, lane, (long)blockIdx.x * TILE_M);
    __syncthreads();

    int i = 0;
    for (long t = blockIdx.x; t < ntiles; t += gridDim.x, i++) {
        const long row0 = t * TILE_M;
        const uint32_t q8cur = q8_base + (i & 1) * 2048;
        const uint32_t q8nxt = q8_base + ((i & 1) ^ 1) * 2048;

        // ====== R2: sim GEMM + exp + e->A tile + row partials ==============
        {
            const int mband = warp & 7;          // 8 bands of 16 rows
            const int nhalf = warp >> 3;         // 2 halves of 128 keys
            const int m0s = mband * 16;

            uint32_t qa0, qa1;
            ldsm_x2(qa0, qa1, q8cur + (m0s + (lane & 15)) * 16);

            #pragma unroll
            for (int nb2 = 0; nb2 < 2; nb2++) {
                const int nband = nhalf * 2 + nb2;
                const int n0s = nband * 64;

                uint32_t kb[8];
                ldsm_x4(kb[0], kb[1], kb[2], kb[3], k_base + (n0s + lane) * 16);
                ldsm_x4(kb[4], kb[5], kb[6], kb[7], k_base + (n0s + 32 + lane) * 16);

                float d[8][4];
                #pragma unroll
                for (int tt = 0; tt < 8; tt++) {
                    d[tt][0] = d[tt][1] = d[tt][2] = d[tt][3] = 0.f;
                    mma16808(d[tt], qa0, qa1, kb[tt]);
                }

                const int rA = m0s + (lane >> 2);
                const uint32_t arow0 = a_base + rA * (AK * 2)
                                     + (n0s + (lane & 3) * 2) * 2;
                const uint32_t arow1 = arow0 + 8 * (AK * 2);
                float sL = 0.f, sH = 0.f;
                const int tmax = (nband == 3) ? 6 : 8;   // mask keys >= 240
                #pragma unroll
                for (int tt = 0; tt < 8; tt++) {
                    if (tt < tmax) {
                        const float e0 = exp2_fast(d[tt][0] - CLOG2E);
                        const float e1 = exp2_fast(d[tt][1] - CLOG2E);
                        const float e2 = exp2_fast(d[tt][2] - CLOG2E);
                        const float e3 = exp2_fast(d[tt][3] - CLOG2E);
                        const __half2 h01 = __floats2half2_rn(e0, e1);
                        const __half2 h23 = __floats2half2_rn(e2, e3);
                        sts_u32(arow0 + tt * 16, *(const uint32_t*)&h01);
                        sts_u32(arow1 + tt * 16, *(const uint32_t*)&h23);
                        sL += e0 + e1;
                        sH += e2 + e3;
                    }
                }
                sL += __shfl_xor_sync(0xffffffffu, sL, 1);
                sL += __shfl_xor_sync(0xffffffffu, sL, 2);
                sH += __shfl_xor_sync(0xffffffffu, sH, 1);
                sH += __shfl_xor_sync(0xffffffffu, sH, 2);
                if ((lane & 3) == 0) {
                    rsp_s[nband * 128 + rA] = sL;
                    rsp_s[nband * 128 + rA + 8] = sH;
                }
            }
        }
        __syncthreads();

        // ====== merged region: R3(t) and R1(t+grid), order alternating ====
        const long nt = t + gridDim.x;
        if (warp & 1) {
            if (nt < ntiles)
                regionR1(query, smem, q8nxt, warp, lane, nt * TILE_M);
            regionR3(content, attn_out, a_base, b_base, rsp_s, warp, lane, row0);
        } else {
            regionR3(content, attn_out, a_base, b_base, rsp_s, warp, lane, row0);
            if (nt < ntiles)
                regionR1(query, smem, q8nxt, warp, lane, nt * TILE_M);
        }
        __syncthreads();
    }
}

// ---------------------------------------------------------------------------
extern "C" void kernel_launch(void* const* d_in, const int* in_sizes, int n_in,
                              void* d_out, int out_size)
{
    const float* query  = (const float*)d_in[0];
    const float* W1     = (const float*)d_in[1];
    const float* b1     = (const float*)d_in[2];
    const float* W2     = (const float*)d_in[3];
    const float* b2     = (const float*)d_in[4];
    const float* values = (const float*)d_in[5];
    const float* keys   = (const float*)d_in[6];

    const int nrows  = in_sizes[0] / DQ;   // 262144
    const int ntiles = (nrows + TILE_M - 1) / TILE_M;

    float* out = (float*)d_out;
    float* content = out;
    float* attn;
    float* scratch;
    cudaGetSymbolAddress((void**)&scratch, g_attn_scratch);
    if ((long)out_size >= (long)nrows * (DV + NS)) {
        attn = out + (long)nrows * DV;
    } else {
        attn = scratch;
    }

    cudaFuncSetAttribute(fused_kernel, cudaFuncAttributeMaxDynamicSharedMemorySize,
                         SMEM_TOTAL);

    fused_kernel<<<152, NTHREADS, SMEM_TOTAL>>>(
        query, W1, b1, W2, b2, values, keys, content, attn, nrows, ntiles);
}